// round 11
// baseline (speedup 1.0000x reference)
#include <cuda_runtime.h>
#include <cuda_bf16.h>
#include <math.h>

#define Nn 50000
#define Ee 800000
#define LDS 136       // smem row stride (bf16 elems) for 128-wide tiles
#define LDSE 40       // smem row stride for 32-wide ef tiles
#define B_EL 16384    // 128*128
#define WL   229376   // per-layer elems in g_w (14 * B_EL)
#define SHS 132       // sH fp32 row stride

// ---------------- scratch (device globals; no allocation allowed) -----------
__device__ float          g_x  [(size_t)Nn*128];
__device__ __nv_bfloat16  g_xbf[(size_t)Nn*128];
__device__ __nv_bfloat16  g_xa [(size_t)Nn*128];
__device__ __nv_bfloat16  g_xb [(size_t)Nn*128];
__device__ float          g_agg[(size_t)Nn*128];   // aggregated h1 (fp32)
__device__ __nv_bfloat16  g_efbf[(size_t)Ee*32];   // ef bf16 (original order)
__device__ __nv_bfloat16  g_ef_s[(size_t)Ee*32];   // ef bf16 (dst-sorted)
__device__ int            g_src_s[Ee];             // src (dst-sorted)
__device__ int            g_dst_s[Ee];             // dst (dst-sorted)
__device__ int            g_degi[Nn];
__device__ int            g_cur[Nn];
__device__ float          g_deg[Nn];
__device__ float          g_red[128];
__device__ float          g_v  [4*128];            // b2 @ U1b per layer
__device__ float          g_be [4*128];            // be @ W1e per layer
__device__ __nv_bfloat16  g_w[(size_t)4*WL];
__device__ __nv_bfloat16  g_wc [(size_t)4*2*B_EL]; // (W2@U1b) hi/lo per layer
__device__ __nv_bfloat16  g_wce[(size_t)4*2*4096]; // (We@W1e) hi/lo per layer [32,128]

// ---------------- mma helpers ------------------------------------------------
__device__ __forceinline__ unsigned sptr(const void* p){
    return (unsigned)__cvta_generic_to_shared((void*)p);
}
__device__ __forceinline__ void ldsmA(unsigned a, unsigned &r0, unsigned &r1,
                                      unsigned &r2, unsigned &r3){
    asm volatile("ldmatrix.sync.aligned.m8n8.x4.shared.b16 {%0,%1,%2,%3},[%4];"
        : "=r"(r0),"=r"(r1),"=r"(r2),"=r"(r3) : "r"(a));
}
__device__ __forceinline__ void ldsmBT(unsigned a, unsigned &r0, unsigned &r1,
                                       unsigned &r2, unsigned &r3){
    asm volatile("ldmatrix.sync.aligned.m8n8.x4.trans.shared.b16 {%0,%1,%2,%3},[%4];"
        : "=r"(r0),"=r"(r1),"=r"(r2),"=r"(r3) : "r"(a));
}
__device__ __forceinline__ void mma_bf16(float* c, unsigned a0, unsigned a1,
                                         unsigned a2, unsigned a3,
                                         unsigned b0, unsigned b1){
    asm volatile("mma.sync.aligned.m16n8k16.row.col.f32.bf16.bf16.f32 "
        "{%0,%1,%2,%3},{%4,%5,%6,%7},{%8,%9},{%0,%1,%2,%3};"
        : "+f"(c[0]),"+f"(c[1]),"+f"(c[2]),"+f"(c[3])
        : "r"(a0),"r"(a1),"r"(a2),"r"(a3),"r"(b0),"r"(b1));
}
__device__ __forceinline__ unsigned packbf(float a, float b){
    __nv_bfloat162 h = __floats2bfloat162_rn(a, b);
    return *(unsigned*)&h;
}

// -------- fused weight pre-split (ONE launch): hi=bf16(w), lo=bf16(w-hi) ----
__global__ void split_all_kernel(const float* __restrict__ msg_w1,
                                 const float* __restrict__ msg_w2,
                                 const float* __restrict__ upd_w1,
                                 const float* __restrict__ upd_w2){
    const int PER_L = 7*B_EL;
    int i = blockIdx.x*blockDim.x + threadIdx.x;
    if (i >= 4*PER_L) return;
    float w; size_t hid; size_t lstep;
    int l = i / PER_L, k = i % PER_L;
    size_t base = (size_t)l*WL;
    if (k < 3*B_EL) {                       // W1a, W1b, W1e
        w = msg_w1[(size_t)l*385*128 + k];
        int blk = k / B_EL, off = k % B_EL;
        hid = base + (size_t)(2*blk)*B_EL + off; lstep = B_EL;
    } else if (k < 4*B_EL) {                // W2
        int off = k - 3*B_EL;
        w = msg_w2[(size_t)l*B_EL + off];
        hid = base + (size_t)6*B_EL + off; lstep = B_EL;
    } else if (k < 6*B_EL) {                // U1 (2 blocks)
        int off = k - 4*B_EL;
        w = upd_w1[(size_t)l*2*B_EL + off];
        hid = base + (size_t)8*B_EL + off; lstep = 2*B_EL;
    } else {                                // U2
        int off = k - 6*B_EL;
        w = upd_w2[(size_t)l*B_EL + off];
        hid = base + (size_t)12*B_EL + off; lstep = B_EL;
    }
    __nv_bfloat16 h = __float2bfloat16(w);
    g_w[hid] = h;
    g_w[hid + lstep] = __float2bfloat16(w - __bfloat162float(h));
}

// -------- ef -> bf16 (once) -------------------------------------------------
__global__ void efconv_kernel(const float* __restrict__ ef){
    size_t i = (size_t)blockIdx.x*blockDim.x + threadIdx.x;
    size_t n = (size_t)Ee*32;
    for (; i < n; i += (size_t)gridDim.x*blockDim.x)
        g_efbf[i] = __float2bfloat16(ef[i]);
}

// -------- composite edge weight: Wce = We@W1e (hi/lo), g_be = be@W1e --------
__global__ void wce_prec_kernel(const float* __restrict__ msg_w1,
                                const float* __restrict__ enc_edge_w,
                                const float* __restrict__ enc_edge_b){
    int idx = blockIdx.x*blockDim.x + threadIdx.x;
    if (idx >= 4*32*128) return;
    int l = idx >> 12; int ij = idx & 4095;
    int i = ij >> 7, j = ij & 127;
    const float* W1e = msg_w1 + (size_t)l*385*128 + 256*128;
    float c = 0.f;
#pragma unroll 4
    for (int k = 0; k < 128; ++k)
        c = fmaf(enc_edge_w[i*128 + k], W1e[k*128 + j], c);
    __nv_bfloat16 h = __float2bfloat16(c);
    g_wce[(size_t)l*8192 + ij] = h;
    g_wce[(size_t)l*8192 + 4096 + ij] = __float2bfloat16(c - __bfloat162float(h));
    if (i == 0) {
        float v = 0.f;
#pragma unroll 4
        for (int k = 0; k < 128; ++k)
            v = fmaf(enc_edge_b[k], W1e[k*128 + j], v);
        g_be[l*128 + j] = v;
    }
}

// -------- composite update weight: C = W2@U1b, v = b2@U1b -------------------
__global__ void wprec_kernel(const float* __restrict__ msg_w2,
                             const float* __restrict__ upd_w1,
                             const float* __restrict__ msg_b2){
    int idx = blockIdx.x*blockDim.x + threadIdx.x;
    if (idx >= 4*B_EL) return;
    int l = idx >> 14; int ij = idx & 16383;
    int i = ij >> 7, j = ij & 127;
    const float* W2  = msg_w2 + (size_t)l*B_EL;
    const float* U1b = upd_w1 + (size_t)l*2*B_EL + B_EL;
    float c = 0.f;
#pragma unroll 4
    for (int k = 0; k < 128; ++k)
        c = fmaf(W2[i*128 + k], U1b[k*128 + j], c);
    __nv_bfloat16 h = __float2bfloat16(c);
    g_wc[(size_t)l*2*B_EL + ij] = h;
    g_wc[(size_t)l*2*B_EL + B_EL + ij] = __float2bfloat16(c - __bfloat162float(h));
    if (i == 0) {
        float v = 0.f;
#pragma unroll 4
        for (int k = 0; k < 128; ++k)
            v = fmaf(msg_b2[l*128 + k], U1b[k*128 + j], v);
        g_v[l*128 + j] = v;
    }
}

// -------- degree histogram + scan + dst-sorted edge arrays ------------------
__global__ void zero_deg_kernel(){
    int i = blockIdx.x*blockDim.x + threadIdx.x;
    if (i < Nn) g_degi[i] = 0;
}
__global__ void deg_accum_kernel(const int* __restrict__ eidx){
    int i = blockIdx.x*blockDim.x + threadIdx.x;
    if (i < Ee) atomicAdd(&g_degi[eidx[(size_t)Ee + i]], 1);
}
// single-block exclusive scan over Nn degrees -> g_cur (cursor), g_deg (float)
__global__ void scan_kernel(){
    __shared__ int sh[1024];
    int t = threadIdx.x;
    const int CH = (Nn + 1023) / 1024;   // 49
    int lo = t*CH, hi = lo + CH; if (hi > Nn) hi = Nn; if (lo > Nn) lo = Nn;
    int sum = 0;
    for (int i = lo; i < hi; ++i) sum += g_degi[i];
    sh[t] = sum;
    __syncthreads();
    for (int off = 1; off < 1024; off <<= 1){
        int v = (t >= off) ? sh[t - off] : 0;
        __syncthreads();
        sh[t] += v;
        __syncthreads();
    }
    int run = sh[t] - sum;   // exclusive prefix
    for (int i = lo; i < hi; ++i){
        g_cur[i] = run;
        g_deg[i] = (float)g_degi[i];
        run += g_degi[i];
    }
}
// scatter edges into dst-sorted arrays (src, dst, ef row)
__global__ void sort_scatter_kernel(const int* __restrict__ eidx){
    int e = blockIdx.x*blockDim.x + threadIdx.x;
    if (e >= Ee) return;
    int dst = eidx[(size_t)Ee + e];
    int pos = atomicAdd(&g_cur[dst], 1);
    g_src_s[pos] = eidx[e];
    g_dst_s[pos] = dst;
    const uint4* s = (const uint4*)(g_efbf + (size_t)e*32);
    uint4* d = (uint4*)(g_ef_s + (size_t)pos*32);
    d[0] = s[0]; d[1] = s[1]; d[2] = s[2]; d[3] = s[3];
}

// Load dense bf16 [128][128] weight into SMEM [128][LDS].  256 threads.
__device__ __forceinline__ void load_wbf(const __nv_bfloat16* __restrict__ Wd,
                                         __nv_bfloat16* sW, int tid){
#pragma unroll
    for (int it = 0; it < 8; ++it){
        int idx = tid + it*256;
        int row = idx >> 4, c = idx & 15;
        *(uint4*)(sW + row*LDS + c*8) = __ldg((const uint4*)Wd + idx);
    }
}

// Warp-level 16x128 @ 128x128 mma accumulate. Warp w owns rows w*16..w*16+15.
__device__ __forceinline__ void mma_gemm128(const __nv_bfloat16* sA,
                                            const __nv_bfloat16* sW,
                                            float acc[16][4], int warp, int lane){
    unsigned aB = sptr(sA + (warp*16 + (lane & 15))*LDS + (lane >> 4)*8);
    unsigned bB = sptr(sW + (lane & 15)*LDS + (lane >> 4)*8);
#pragma unroll
    for (int kk = 0; kk < 8; ++kk){
        unsigned a0,a1,a2,a3;
        ldsmA(aB + kk*32, a0,a1,a2,a3);
#pragma unroll
        for (int jp = 0; jp < 8; ++jp){
            unsigned b0,b1,b2,b3;
            ldsmBT(bB + kk*(16*LDS*2) + jp*32, b0,b1,b2,b3);
            mma_bf16(acc[2*jp],   a0,a1,a2,a3, b0,b1);
            mma_bf16(acc[2*jp+1], a0,a1,a2,a3, b2,b3);
        }
    }
}

// ---------------- node encoder (fp32 FFMA) ----------------------------------
__global__ void enc_nodes_kernel(const float* __restrict__ nf,
                                 const float* __restrict__ W,
                                 const float* __restrict__ b) {
    extern __shared__ float sm[];
    float* sIn = sm;
    float* sW  = sm + 64*64;
    int tid = threadIdx.x, warp = tid >> 5, lane = tid & 31;
    int rb = blockIdx.x * 64;
#pragma unroll
    for (int it = 0; it < 4; ++it) {
        int idx = tid + it*256;
        int row = idx >> 4, c4 = idx & 15;
        int r = rb + row; if (r >= Nn) r = Nn - 1;
        ((float4*)sIn)[idx] = ((const float4*)(nf + (size_t)r*64))[c4];
    }
#pragma unroll
    for (int it = 0; it < 8; ++it) {
        int idx = tid + it*256;
        ((float4*)sW)[idx] = ((const float4*)W)[idx];
    }
    __syncthreads();
    float acc[8][4];
#pragma unroll
    for (int i = 0; i < 8; ++i) { acc[i][0]=acc[i][1]=acc[i][2]=acc[i][3]=0.f; }
#pragma unroll 8
    for (int k = 0; k < 64; ++k) {
        float4 w = ((float4*)(sW + k*128))[lane];
#pragma unroll
        for (int i = 0; i < 8; ++i) {
            float a = sIn[(warp*8 + i)*64 + k];
            acc[i][0] = fmaf(a, w.x, acc[i][0]);
            acc[i][1] = fmaf(a, w.y, acc[i][1]);
            acc[i][2] = fmaf(a, w.z, acc[i][2]);
            acc[i][3] = fmaf(a, w.w, acc[i][3]);
        }
    }
    float4 bb = ((const float4*)b)[lane];
#pragma unroll
    for (int i = 0; i < 8; ++i) {
        int r = rb + warp*8 + i;
        if (r < Nn) {
            float4 v = make_float4(acc[i][0]+bb.x, acc[i][1]+bb.y,
                                   acc[i][2]+bb.z, acc[i][3]+bb.w);
            ((float4*)(g_x + (size_t)r*128))[lane] = v;
            *(uint2*)(g_xbf + (size_t)r*128 + lane*4) =
                make_uint2(packbf(v.x, v.y), packbf(v.z, v.w));
        }
    }
}

// --------- per-layer node precompute + agg zero -----------------------------
__global__ void __launch_bounds__(256,2) node_pre_mma(const float* __restrict__ cong,
                                 const float* __restrict__ w1l,
                                 const float* __restrict__ b1,
                                 int layer) {
    extern __shared__ __nv_bfloat16 smx[];
    __nv_bfloat16* sA = smx;
    __nv_bfloat16* sW = smx + 128*LDS;
    const __nv_bfloat16* wb = g_w + (size_t)layer*WL;
    int tid = threadIdx.x, warp = tid >> 5, lane = tid & 31;
    int rb = blockIdx.x * 128;
    float4 z4 = make_float4(0.f,0.f,0.f,0.f);
#pragma unroll
    for (int it = 0; it < 16; ++it) {
        int idx = tid + it*256;
        int row = idx >> 5, c4 = idx & 31;
        int r = rb + row;
        if (r < Nn) ((float4*)(g_agg + (size_t)r*128))[c4] = z4;
    }
#pragma unroll
    for (int it = 0; it < 8; ++it) {
        int idx = tid + it*256; int row = idx >> 4, c = idx & 15;
        int r = rb + row; if (r >= Nn) r = Nn - 1;
        *(uint4*)(sA + row*LDS + c*8) = __ldg((const uint4*)(g_xbf + (size_t)r*128) + c);
    }
    float acc[16][4];
#pragma unroll
    for (int j = 0; j < 16; ++j) { acc[j][0]=acc[j][1]=acc[j][2]=acc[j][3]=0.f; }
#pragma unroll 1
    for (int ph = 0; ph < 2; ++ph) {
        __syncthreads();
        load_wbf(wb + (size_t)ph*B_EL, sW, tid);
        __syncthreads();
        mma_gemm128(sA, sW, acc, warp, lane);
    }
    int g = lane >> 2, t4 = lane & 3;
    int r0 = rb + warp*16 + g, r1 = r0 + 8;
    float c0 = cong[r0 < Nn ? r0 : Nn-1];
    float c1 = cong[r1 < Nn ? r1 : Nn-1];
#pragma unroll
    for (int j = 0; j < 16; ++j) {
        int col = j*8 + t4*2;
        float2 wc = *(const float2*)(w1l + 384*128 + col);
        float2 bb = *(const float2*)(b1 + col);
        float2 be = *(const float2*)(g_be + layer*128 + col);
        bb.x += be.x; bb.y += be.y;
        if (r0 < Nn)
            *(unsigned*)(g_xa + (size_t)r0*128 + col) =
                packbf(acc[j][0] + c0*wc.x + bb.x, acc[j][1] + c0*wc.y + bb.y);
        if (r1 < Nn)
            *(unsigned*)(g_xa + (size_t)r1*128 + col) =
                packbf(acc[j][2] + c1*wc.x + bb.x, acc[j][3] + c1*wc.y + bb.y);
        acc[j][0]=acc[j][1]=acc[j][2]=acc[j][3]=0.f;
    }
#pragma unroll 1
    for (int ph = 0; ph < 2; ++ph) {
        __syncthreads();
        load_wbf(wb + (size_t)(2+ph)*B_EL, sW, tid);
        __syncthreads();
        mma_gemm128(sA, sW, acc, warp, lane);
    }
#pragma unroll
    for (int j = 0; j < 16; ++j) {
        int col = j*8 + t4*2;
        if (r0 < Nn)
            *(unsigned*)(g_xb + (size_t)r0*128 + col) = packbf(acc[j][0], acc[j][1]);
        if (r1 < Nn)
            *(unsigned*)(g_xb + (size_t)r1*128 + col) = packbf(acc[j][2], acc[j][3]);
    }
}

__global__ void zero_red_kernel() { if (threadIdx.x < 128) g_red[threadIdx.x] = 0.f; }

// ------- persistent edge kernel: dst-sorted tiles + segmented reduce --------
// h1 = relu(ef_s@Wce + xa[src_s] + xb[dst_s]); agg[dst] += segmented-sum(h1)
__global__ void __launch_bounds__(256,2) edge_persist_kernel(int layer) {
    extern __shared__ __nv_bfloat16 smx[];
    __nv_bfloat16* sEF = smx;                       // 128 x LDSE bf16 (10240 B)
    __nv_bfloat16* sW  = smx + 128*LDSE;            // 64 x LDS bf16  (17408 B)
    float* sH = (float*)(smx + 128*LDSE + 64*LDS);  // 128 x SHS fp32 (67584 B)
    __shared__ int sSe[128], sDe[128];
    int tid = threadIdx.x, w = tid >> 5, lane = tid & 31;

    // composite weight hi/lo: 64 rows x 16 uint4
#pragma unroll
    for (int it = 0; it < 4; ++it) {
        int idx = tid + it*256;
        int row = idx >> 4, c = idx & 15;
        *(uint4*)(sW + row*LDS + c*8) =
            __ldg((const uint4*)(g_wce + (size_t)layer*8192) + idx);
    }

    int g = lane >> 2, t4 = lane & 3;

    for (int t = blockIdx.x; t < Ee/128; t += gridDim.x) {
        size_t eb = (size_t)t * 128;
        __syncthreads();                      // prev tile phase2 done
        if (tid < 128) {
            sSe[tid] = g_src_s[eb + tid];
            sDe[tid] = g_dst_s[eb + tid];
        }
        // ef tile: 512 uint4 (sequential!)
#pragma unroll
        for (int it = 0; it < 2; ++it) {
            int idx = tid + it*256; int row = idx >> 2, c = idx & 3;
            *(uint4*)(sEF + row*LDSE + c*8) =
                __ldg((const uint4*)(g_ef_s + eb*32) + idx);
        }
        __syncthreads();                      // indices + ef visible
        float acc[16][4];
#pragma unroll
        for (int j = 0; j < 16; ++j) { acc[j][0]=acc[j][1]=acc[j][2]=acc[j][3]=0.f; }
        // GEMM: K=32, hi + lo parts
        unsigned aB = sptr(sEF + (w*16 + (lane & 15))*LDSE + (lane >> 4)*8);
#pragma unroll
        for (int part = 0; part < 2; ++part) {
            unsigned bB = sptr(sW + (part*32 + (lane & 15))*LDS + (lane >> 4)*8);
#pragma unroll
            for (int kk = 0; kk < 2; ++kk) {
                unsigned a0,a1,a2,a3;
                ldsmA(aB + kk*32, a0,a1,a2,a3);
#pragma unroll
                for (int jp = 0; jp < 8; ++jp) {
                    unsigned b0,b1,b2,b3;
                    ldsmBT(bB + kk*(16*LDS*2) + jp*32, b0,b1,b2,b3);
                    mma_bf16(acc[2*jp],   a0,a1,a2,a3, b0,b1);
                    mma_bf16(acc[2*jp+1], a0,a1,a2,a3, b2,b3);
                }
            }
        }
        // gather xa[src]+xb[dst] -> sH (fp32)
#pragma unroll
        for (int k = 0; k < 8; ++k) {
            int idx = tid + k*256; int row = idx >> 4, c = idx & 15;
            uint4 a = __ldg((const uint4*)(g_xa + (size_t)sSe[row]*128) + c);
            uint4 b = __ldg((const uint4*)(g_xb + (size_t)sDe[row]*128) + c);
            float* hp = sH + row*SHS + c*8;
            unsigned av[4] = {a.x,a.y,a.z,a.w}, bv[4] = {b.x,b.y,b.z,b.w};
#pragma unroll
            for (int p = 0; p < 4; ++p) {
                float2 fa = __bfloat1622float2(*(__nv_bfloat162*)&av[p]);
                float2 fb = __bfloat1622float2(*(__nv_bfloat162*)&bv[p]);
                hp[2*p]   = fa.x + fb.x;
                hp[2*p+1] = fa.y + fb.y;
            }
        }
        __syncthreads();                      // sH gather + GEMM done
        // h1 = relu(acc + sH) -> sH
#pragma unroll
        for (int j = 0; j < 16; ++j) {
            int col = j*8 + t4*2;
            int row0 = w*16 + g, row1 = row0 + 8;
            float2* p0 = (float2*)(sH + row0*SHS + col);
            float2* p1 = (float2*)(sH + row1*SHS + col);
            float2 v0 = *p0, v1 = *p1;
            v0.x = fmaxf(acc[j][0] + v0.x, 0.f);
            v0.y = fmaxf(acc[j][1] + v0.y, 0.f);
            v1.x = fmaxf(acc[j][2] + v1.x, 0.f);
            v1.y = fmaxf(acc[j][3] + v1.y, 0.f);
            *p0 = v0; *p1 = v1;
        }
        __syncthreads();                      // h1 complete
        // phase 2: segmented column sum (thread = column, walk 64 rows)
        {
            int c = tid & 127, half = tid >> 7;
            int r0 = half*64;
            float s = 0.f;
            int cur = sDe[r0];
#pragma unroll 4
            for (int r = r0; r < r0 + 64; ++r) {
                int d = sDe[r];
                if (d != cur) {
                    atomicAdd(g_agg + (size_t)cur*128 + c, s);
                    s = 0.f; cur = d;
                }
                s += sH[r*SHS + c];
            }
            atomicAdd(g_agg + (size_t)cur*128 + c, s);
        }
    }
}

// ------- update (mma): x = LN(x + MLP2(relu(x@U1a + aggH@C + deg*v + ub1))) -
__global__ void __launch_bounds__(256,2) update_mma(const float* __restrict__ ub1,
                               const float* __restrict__ ub2,
                               const float* __restrict__ lw,
                               const float* __restrict__ lb,
                               int layer) {
    extern __shared__ __nv_bfloat16 smx[];
    __nv_bfloat16* sA = smx;
    __nv_bfloat16* sW = smx + 128*LDS;
    const __nv_bfloat16* wb = g_w + (size_t)layer*WL;
    int tid = threadIdx.x, warp = tid >> 5, lane = tid & 31;
    int rb = blockIdx.x * 128;
    float acc[16][4];
#pragma unroll
    for (int j = 0; j < 16; ++j) { acc[j][0]=acc[j][1]=acc[j][2]=acc[j][3]=0.f; }
#pragma unroll 1
    for (int kc = 0; kc < 2; ++kc) {
        __syncthreads();
        if (kc == 0) {
#pragma unroll
            for (int it = 0; it < 8; ++it) {
                int idx = tid + it*256; int row = idx >> 4, c = idx & 15;
                int r = rb + row; if (r >= Nn) r = Nn - 1;
                *(uint4*)(sA + row*LDS + c*8) =
                    __ldg((const uint4*)(g_xbf + (size_t)r*128) + c);
            }
        } else {
#pragma unroll
            for (int it = 0; it < 16; ++it) {
                int idx = tid + it*256; int row = idx >> 5, c4 = idx & 31;
                int r = rb + row; if (r >= Nn) r = Nn - 1;
                float4 w = __ldg((const float4*)(g_agg + (size_t)r*128) + c4);
                *(uint2*)(sA + row*LDS + c4*4) =
                    make_uint2(packbf(w.x, w.y), packbf(w.z, w.w));
            }
        }
#pragma unroll 1
        for (int ph = 0; ph < 2; ++ph) {
            __syncthreads();
            const __nv_bfloat16* ws = (kc == 0)
                ? wb + (size_t)(8 + ph*2)*B_EL
                : g_wc + (size_t)layer*2*B_EL + (size_t)ph*B_EL;
            load_wbf(ws, sW, tid);
            __syncthreads();
            mma_gemm128(sA, sW, acc, warp, lane);
        }
    }
    __syncthreads();
    int g = lane >> 2, t4 = lane & 3;
    int r0 = rb + warp*16 + g, r1 = r0 + 8;
    int r0c = r0 < Nn ? r0 : Nn-1, r1c = r1 < Nn ? r1 : Nn-1;
    float dg0 = g_deg[r0c], dg1 = g_deg[r1c];
#pragma unroll
    for (int j = 0; j < 16; ++j) {
        int col = j*8 + t4*2;
        float2 bb = *(const float2*)(ub1 + col);
        float2 vv = *(const float2*)(g_v + layer*128 + col);
#pragma unroll
        for (int rr = 0; rr < 2; ++rr) {
            int row = warp*16 + g + rr*8;
            float dg = rr ? dg1 : dg0;
            float h0 = fmaxf(acc[j][2*rr]   + bb.x + dg*vv.x, 0.f);
            float h1 = fmaxf(acc[j][2*rr+1] + bb.y + dg*vv.y, 0.f);
            *(unsigned*)(sA + row*LDS + col) = packbf(h0, h1);
            acc[j][2*rr] = 0.f; acc[j][2*rr+1] = 0.f;
        }
    }
#pragma unroll 1
    for (int ph = 0; ph < 2; ++ph) {
        __syncthreads();
        load_wbf(wb + (size_t)(12 + ph)*B_EL, sW, tid);
        __syncthreads();
        mma_gemm128(sA, sW, acc, warp, lane);
    }
    float s0 = 0.f, s1 = 0.f;
#pragma unroll
    for (int j = 0; j < 16; ++j) {
        int col = j*8 + t4*2;
        float2 bb = *(const float2*)(ub2 + col);
        float2 x0 = *(const float2*)(g_x + (size_t)r0c*128 + col);
        float2 x1 = *(const float2*)(g_x + (size_t)r1c*128 + col);
        acc[j][0] += x0.x + bb.x;  acc[j][1] += x0.y + bb.y;
        acc[j][2] += x1.x + bb.x;  acc[j][3] += x1.y + bb.y;
        s0 += acc[j][0] + acc[j][1];
        s1 += acc[j][2] + acc[j][3];
    }
    s0 += __shfl_xor_sync(0xffffffffu, s0, 1);
    s0 += __shfl_xor_sync(0xffffffffu, s0, 2);
    s1 += __shfl_xor_sync(0xffffffffu, s1, 1);
    s1 += __shfl_xor_sync(0xffffffffu, s1, 2);
    float mu0 = s0 * (1.f/128.f), mu1 = s1 * (1.f/128.f);
    float q0 = 0.f, q1 = 0.f;
#pragma unroll
    for (int j = 0; j < 16; ++j) {
        float d0 = acc[j][0]-mu0, d1 = acc[j][1]-mu0;
        float d2 = acc[j][2]-mu1, d3 = acc[j][3]-mu1;
        q0 += d0*d0 + d1*d1;
        q1 += d2*d2 + d3*d3;
    }
    q0 += __shfl_xor_sync(0xffffffffu, q0, 1);
    q0 += __shfl_xor_sync(0xffffffffu, q0, 2);
    q1 += __shfl_xor_sync(0xffffffffu, q1, 1);
    q1 += __shfl_xor_sync(0xffffffffu, q1, 2);
    float rstd0 = rsqrtf(q0 * (1.f/128.f) + 1e-5f);
    float rstd1 = rsqrtf(q1 * (1.f/128.f) + 1e-5f);
#pragma unroll
    for (int j = 0; j < 16; ++j) {
        int col = j*8 + t4*2;
        float2 lw2 = *(const float2*)(lw + col);
        float2 lb2 = *(const float2*)(lb + col);
        if (r0 < Nn) {
            float o0 = (acc[j][0]-mu0)*rstd0*lw2.x + lb2.x;
            float o1 = (acc[j][1]-mu0)*rstd0*lw2.y + lb2.y;
            *(float2*)(g_x + (size_t)r0*128 + col) = make_float2(o0, o1);
            *(unsigned*)(g_xbf + (size_t)r0*128 + col) = packbf(o0, o1);
        }
        if (r1 < Nn) {
            float o2 = (acc[j][2]-mu1)*rstd1*lw2.x + lb2.x;
            float o3 = (acc[j][3]-mu1)*rstd1*lw2.y + lb2.y;
            *(float2*)(g_x + (size_t)r1*128 + col) = make_float2(o2, o3);
            *(unsigned*)(g_xbf + (size_t)r1*128 + col) = packbf(o2, o3);
        }
    }
}

// ---------------- column-sum reduce + readout -------------------------------
__global__ void reduce_kernel() {
    int j = threadIdx.x;
    int chunk = (Nn + gridDim.x - 1) / gridDim.x;
    int r0 = blockIdx.x * chunk;
    int r1 = r0 + chunk; if (r1 > Nn) r1 = Nn;
    float s = 0.f;
    for (int r = r0; r < r1; ++r) s += g_x[(size_t)r*128 + j];
    atomicAdd(&g_red[j], s);
}

__global__ void final_kernel(const void* __restrict__ maskp,
                             const float* __restrict__ uw1, const float* __restrict__ ub1f,
                             const float* __restrict__ uw2, const float* __restrict__ ub2f,
                             const float* __restrict__ rw1, const float* __restrict__ rb1,
                             const float* __restrict__ rw2, const float* __restrict__ rb2,
                             const float* __restrict__ rw3, const float* __restrict__ rb3,
                             float* __restrict__ out) {
    __shared__ float sge[128], s1[128], s2[128];
    __shared__ int c1s, c2s;
    __shared__ float sufs;
    int j = threadIdx.x;
    if (j == 0) { c1s = 0; c2s = 0; sufs = 0.f; }
    __syncthreads();
    const unsigned char* mb = (const unsigned char*)maskp;
    int c1 = 0, c2 = 0;
    for (int i = j; i < Nn; i += 128) {
        unsigned char v = mb[i];
        if (v) { if ((i & 3) == 0) c1++; else c2++; }
    }
    atomicAdd(&c1s, c1); atomicAdd(&c2s, c2);
    __syncthreads();
    float s = 0.f;
    if (c2s == 0) {
        const int* mi = (const int*)maskp;
        for (int i = j; i < Nn; i += 128) s += (mi[i] != 0) ? 1.f : 0.f;
    } else if (c1s == 0) {
        const float* mf = (const float*)maskp;
        for (int i = j; i < Nn; i += 128) s += mf[i];
    } else {
        for (int i = j; i < Nn; i += 128) s += mb[i] ? 1.f : 0.f;
    }
    atomicAdd(&sufs, s);
    sge[j] = g_red[j] * (1.f/(float)Nn);
    __syncthreads();
    float uf = sufs * (1.f/(float)Nn);
    s1[j] = fmaxf(uf * uw1[j] + ub1f[j], 0.f);
    __syncthreads();
    float t = ub2f[j];
    for (int k = 0; k < 128; ++k) t = fmaf(s1[k], uw2[k*128 + j], t);
    s2[j] = t;
    __syncthreads();
    float h = rb1[j];
    for (int k = 0; k < 128; ++k) h = fmaf(sge[k], rw1[k*128 + j], h);
    for (int k = 0; k < 128; ++k) h = fmaf(s2[k], rw1[(128 + k)*128 + j], h);
    s1[j] = fmaxf(h, 0.f);
    __syncthreads();
    if (j < 64) {
        float gv = rb2[j];
        for (int k = 0; k < 128; ++k) gv = fmaf(s1[k], rw2[k*64 + j], gv);
        s2[j] = fmaxf(gv, 0.f);
    }
    __syncthreads();
    if (j == 0) {
        float o = rb3[0];
        for (int k = 0; k < 64; ++k) o = fmaf(s2[k], rw3[k], o);
        out[0] = 1.f / (1.f + expf(-o));
    }
}

// ---------------- launch -----------------------------------------------------
extern "C" void kernel_launch(void* const* d_in, const int* in_sizes, int n_in,
                              void* d_out, int out_size) {
    const float* nf        = (const float*)d_in[0];
    const float* ef        = (const float*)d_in[1];
    const float* cong      = (const float*)d_in[2];
    const int*   eidx      = (const int*)d_in[3];
    const void*  mask      = d_in[4];
    const float* enc_node_w = (const float*)d_in[5];
    const float* enc_node_b = (const float*)d_in[6];
    const float* enc_edge_w = (const float*)d_in[7];
    const float* enc_edge_b = (const float*)d_in[8];
    const float* msg_w1 = (const float*)d_in[9];
    const float* msg_b1 = (const float*)d_in[10];
    const float* msg_w2 = (const float*)d_in[11];
    const float* msg_b2 = (const float*)d_in[12];
    const float* upd_w1 = (const float*)d_in[13];
    const float* upd_b1 = (const float*)d_in[14];
    const float* upd_w2 = (const float*)d_in[15];
    const float* upd_b2 = (const float*)d_in[16];
    const float* ln_w   = (const float*)d_in[17];
    const float* ln_b   = (const float*)d_in[18];
    const float* unr_w1 = (const float*)d_in[19];
    const float* unr_b1 = (const float*)d_in[20];
    const float* unr_w2 = (const float*)d_in[21];
    const float* unr_b2 = (const float*)d_in[22];
    const float* ro_w1  = (const float*)d_in[23];
    const float* ro_b1  = (const float*)d_in[24];
    const float* ro_w2  = (const float*)d_in[25];
    const float* ro_b2  = (const float*)d_in[26];
    const float* ro_w3  = (const float*)d_in[27];
    const float* ro_b3  = (const float*)d_in[28];
    float* out = (float*)d_out;

    const int SM_ENC_N = (64*64 + 64*128) * 4;
    const int SM_MMA2  = 2 * 128 * LDS * 2;                         // 69632 B
    const int SM_EDGE  = (128*LDSE + 64*LDS)*2 + 128*SHS*4;         // 95232 B

    cudaFuncSetAttribute(enc_nodes_kernel,    cudaFuncAttributeMaxDynamicSharedMemorySize, SM_ENC_N);
    cudaFuncSetAttribute(node_pre_mma,        cudaFuncAttributeMaxDynamicSharedMemorySize, SM_MMA2);
    cudaFuncSetAttribute(edge_persist_kernel, cudaFuncAttributeMaxDynamicSharedMemorySize, SM_EDGE);
    cudaFuncSetAttribute(update_mma,          cudaFuncAttributeMaxDynamicSharedMemorySize, SM_MMA2);

    const int SPLIT_TOTAL = 4*7*B_EL;
    const int ENC_N_BLOCKS = (Nn + 63) / 64;
    const int NODE_BLOCKS  = (Nn + 127) / 128;

    split_all_kernel<<<(SPLIT_TOTAL + 255)/256, 256>>>(
        msg_w1, msg_w2, upd_w1, upd_w2);
    efconv_kernel<<<2048, 256>>>(ef);
    enc_nodes_kernel<<<ENC_N_BLOCKS, 256, SM_ENC_N>>>(nf, enc_node_w, enc_node_b);
    wce_prec_kernel<<<(4*32*128 + 255)/256, 256>>>(msg_w1, enc_edge_w, enc_edge_b);
    zero_deg_kernel<<<(Nn + 1023)/1024, 1024>>>();
    deg_accum_kernel<<<(Ee + 255)/256, 256>>>(eidx);
    scan_kernel<<<1, 1024>>>();
    sort_scatter_kernel<<<(Ee + 255)/256, 256>>>(eidx);
    wprec_kernel<<<(4*B_EL + 255)/256, 256>>>(msg_w2, upd_w1, msg_b2);

    for (int l = 0; l < 4; ++l) {
        node_pre_mma<<<NODE_BLOCKS, 256, SM_MMA2>>>(
            cong, msg_w1 + (size_t)l*385*128, msg_b1 + (size_t)l*128, l);
        edge_persist_kernel<<<296, 256, SM_EDGE>>>(l);
        update_mma<<<NODE_BLOCKS, 256, SM_MMA2>>>(
            upd_b1 + (size_t)l*128, upd_b2 + (size_t)l*128,
            ln_w + (size_t)l*128, ln_b + (size_t)l*128, l);
    }

    zero_red_kernel<<<1, 128>>>();
    reduce_kernel<<<250, 128>>>();
    final_kernel<<<1, 128>>>(mask, unr_w1, unr_b1, unr_w2, unr_b2,
                             ro_w1, ro_b1, ro_w2, ro_b2, ro_w3, ro_b3, out);
}

// round 12
// speedup vs baseline: 1.1753x; 1.1753x over previous
#include <cuda_runtime.h>
#include <cuda_bf16.h>
#include <math.h>

#define Nn 50000
#define Ee 800000
#define LDS 136       // smem row stride (bf16 elems) for 128-wide tiles
#define LDSE 40       // smem row stride for 32-wide ef tiles
#define B_EL 16384    // 128*128
#define WL   229376   // per-layer elems in g_w (14 * B_EL)

// ---------------- scratch (device globals; no allocation allowed) -----------
__device__ float          g_x  [(size_t)Nn*128];
__device__ __nv_bfloat16  g_xbf[(size_t)Nn*128];
__device__ __nv_bfloat16  g_xa [(size_t)Nn*128];
__device__ __nv_bfloat16  g_xb [(size_t)Nn*128];
__device__ float          g_agg[(size_t)Nn*128];   // aggregated h1 (fp32)
__device__ __nv_bfloat16  g_efbf[(size_t)Ee*32];   // ef in bf16
__device__ float          g_red[128];
__device__ float          g_deg[Nn];
__device__ float          g_v  [4*128];            // b2 @ U1b per layer
__device__ float          g_be [4*128];            // be @ W1e per layer
__device__ __nv_bfloat16  g_w[(size_t)4*WL];
__device__ __nv_bfloat16  g_wc [(size_t)4*2*B_EL]; // (W2@U1b) hi/lo per layer
__device__ __nv_bfloat16  g_wce[(size_t)4*2*4096]; // (We@W1e) hi/lo per layer [32,128]

// ---------------- mma helpers ------------------------------------------------
__device__ __forceinline__ unsigned sptr(const void* p){
    return (unsigned)__cvta_generic_to_shared((void*)p);
}
__device__ __forceinline__ void ldsmA(unsigned a, unsigned &r0, unsigned &r1,
                                      unsigned &r2, unsigned &r3){
    asm volatile("ldmatrix.sync.aligned.m8n8.x4.shared.b16 {%0,%1,%2,%3},[%4];"
        : "=r"(r0),"=r"(r1),"=r"(r2),"=r"(r3) : "r"(a));
}
__device__ __forceinline__ void ldsmBT(unsigned a, unsigned &r0, unsigned &r1,
                                       unsigned &r2, unsigned &r3){
    asm volatile("ldmatrix.sync.aligned.m8n8.x4.trans.shared.b16 {%0,%1,%2,%3},[%4];"
        : "=r"(r0),"=r"(r1),"=r"(r2),"=r"(r3) : "r"(a));
}
__device__ __forceinline__ void mma_bf16(float* c, unsigned a0, unsigned a1,
                                         unsigned a2, unsigned a3,
                                         unsigned b0, unsigned b1){
    asm volatile("mma.sync.aligned.m16n8k16.row.col.f32.bf16.bf16.f32 "
        "{%0,%1,%2,%3},{%4,%5,%6,%7},{%8,%9},{%0,%1,%2,%3};"
        : "+f"(c[0]),"+f"(c[1]),"+f"(c[2]),"+f"(c[3])
        : "r"(a0),"r"(a1),"r"(a2),"r"(a3),"r"(b0),"r"(b1));
}
__device__ __forceinline__ unsigned packbf(float a, float b){
    __nv_bfloat162 h = __floats2bfloat162_rn(a, b);
    return *(unsigned*)&h;
}
__device__ __forceinline__ float2 unpackbf(unsigned u){
    __nv_bfloat162 h = *(__nv_bfloat162*)&u;
    return make_float2(__bfloat162float(h.x), __bfloat162float(h.y));
}
__device__ __forceinline__ void red4(float* p, float a, float b, float c, float d){
    asm volatile("red.global.add.v4.f32 [%0], {%1,%2,%3,%4};"
        :: "l"(p), "f"(a), "f"(b), "f"(c), "f"(d) : "memory");
}

// -------- fused weight pre-split (ONE launch): hi=bf16(w), lo=bf16(w-hi) ----
__global__ void split_all_kernel(const float* __restrict__ msg_w1,
                                 const float* __restrict__ msg_w2,
                                 const float* __restrict__ upd_w1,
                                 const float* __restrict__ upd_w2){
    const int PER_L = 7*B_EL;
    int i = blockIdx.x*blockDim.x + threadIdx.x;
    if (i >= 4*PER_L) return;
    float w; size_t hid; size_t lstep;
    int l = i / PER_L, k = i % PER_L;
    size_t base = (size_t)l*WL;
    if (k < 3*B_EL) {                       // W1a, W1b, W1e
        w = msg_w1[(size_t)l*385*128 + k];
        int blk = k / B_EL, off = k % B_EL;
        hid = base + (size_t)(2*blk)*B_EL + off; lstep = B_EL;
    } else if (k < 4*B_EL) {                // W2
        int off = k - 3*B_EL;
        w = msg_w2[(size_t)l*B_EL + off];
        hid = base + (size_t)6*B_EL + off; lstep = B_EL;
    } else if (k < 6*B_EL) {                // U1 (2 blocks)
        int off = k - 4*B_EL;
        w = upd_w1[(size_t)l*2*B_EL + off];
        hid = base + (size_t)8*B_EL + off; lstep = 2*B_EL;
    } else {                                // U2
        int off = k - 6*B_EL;
        w = upd_w2[(size_t)l*B_EL + off];
        hid = base + (size_t)12*B_EL + off; lstep = B_EL;
    }
    __nv_bfloat16 h = __float2bfloat16(w);
    g_w[hid] = h;
    g_w[hid + lstep] = __float2bfloat16(w - __bfloat162float(h));
}

// -------- ef -> bf16 (once) -------------------------------------------------
__global__ void efconv_kernel(const float* __restrict__ ef){
    size_t i = (size_t)blockIdx.x*blockDim.x + threadIdx.x;
    size_t n = (size_t)Ee*32;
    for (; i < n; i += (size_t)gridDim.x*blockDim.x)
        g_efbf[i] = __float2bfloat16(ef[i]);
}

// -------- composite edge weight: Wce = We@W1e (hi/lo), g_be = be@W1e --------
__global__ void wce_prec_kernel(const float* __restrict__ msg_w1,
                                const float* __restrict__ enc_edge_w,
                                const float* __restrict__ enc_edge_b){
    int idx = blockIdx.x*blockDim.x + threadIdx.x;
    if (idx >= 4*32*128) return;
    int l = idx >> 12; int ij = idx & 4095;
    int i = ij >> 7, j = ij & 127;
    const float* W1e = msg_w1 + (size_t)l*385*128 + 256*128;
    float c = 0.f;
#pragma unroll 4
    for (int k = 0; k < 128; ++k)
        c = fmaf(enc_edge_w[i*128 + k], W1e[k*128 + j], c);
    __nv_bfloat16 h = __float2bfloat16(c);
    g_wce[(size_t)l*8192 + ij] = h;
    g_wce[(size_t)l*8192 + 4096 + ij] = __float2bfloat16(c - __bfloat162float(h));
    if (i == 0) {
        float v = 0.f;
#pragma unroll 4
        for (int k = 0; k < 128; ++k)
            v = fmaf(enc_edge_b[k], W1e[k*128 + j], v);
        g_be[l*128 + j] = v;
    }
}

// -------- composite update weight: C = W2@U1b, v = b2@U1b -------------------
__global__ void wprec_kernel(const float* __restrict__ msg_w2,
                             const float* __restrict__ upd_w1,
                             const float* __restrict__ msg_b2){
    int idx = blockIdx.x*blockDim.x + threadIdx.x;
    if (idx >= 4*B_EL) return;
    int l = idx >> 14; int ij = idx & 16383;
    int i = ij >> 7, j = ij & 127;
    const float* W2  = msg_w2 + (size_t)l*B_EL;
    const float* U1b = upd_w1 + (size_t)l*2*B_EL + B_EL;
    float c = 0.f;
#pragma unroll 4
    for (int k = 0; k < 128; ++k)
        c = fmaf(W2[i*128 + k], U1b[k*128 + j], c);
    __nv_bfloat16 h = __float2bfloat16(c);
    g_wc[(size_t)l*2*B_EL + ij] = h;
    g_wc[(size_t)l*2*B_EL + B_EL + ij] = __float2bfloat16(c - __bfloat162float(h));
    if (i == 0) {
        float v = 0.f;
#pragma unroll 4
        for (int k = 0; k < 128; ++k)
            v = fmaf(msg_b2[l*128 + k], U1b[k*128 + j], v);
        g_v[l*128 + j] = v;
    }
}

// -------- degree (once) -----------------------------------------------------
__global__ void zero_deg_kernel(){
    int i = blockIdx.x*blockDim.x + threadIdx.x;
    if (i < Nn) g_deg[i] = 0.f;
}
__global__ void deg_accum_kernel(const int* __restrict__ eidx){
    int i = blockIdx.x*blockDim.x + threadIdx.x;
    if (i < Ee) atomicAdd(&g_deg[eidx[(size_t)Ee + i]], 1.f);
}

// Load dense bf16 [128][128] weight into SMEM [128][LDS].  256 threads.
__device__ __forceinline__ void load_wbf(const __nv_bfloat16* __restrict__ Wd,
                                         __nv_bfloat16* sW, int tid){
#pragma unroll
    for (int it = 0; it < 8; ++it){
        int idx = tid + it*256;
        int row = idx >> 4, c = idx & 15;
        *(uint4*)(sW + row*LDS + c*8) = __ldg((const uint4*)Wd + idx);
    }
}

// Warp-level 16x128 @ 128x128 mma accumulate. Warp w owns rows w*16..w*16+15.
__device__ __forceinline__ void mma_gemm128(const __nv_bfloat16* sA,
                                            const __nv_bfloat16* sW,
                                            float acc[16][4], int warp, int lane){
    unsigned aB = sptr(sA + (warp*16 + (lane & 15))*LDS + (lane >> 4)*8);
    unsigned bB = sptr(sW + (lane & 15)*LDS + (lane >> 4)*8);
#pragma unroll
    for (int kk = 0; kk < 8; ++kk){
        unsigned a0,a1,a2,a3;
        ldsmA(aB + kk*32, a0,a1,a2,a3);
#pragma unroll
        for (int jp = 0; jp < 8; ++jp){
            unsigned b0,b1,b2,b3;
            ldsmBT(bB + kk*(16*LDS*2) + jp*32, b0,b1,b2,b3);
            mma_bf16(acc[2*jp],   a0,a1,a2,a3, b0,b1);
            mma_bf16(acc[2*jp+1], a0,a1,a2,a3, b2,b3);
        }
    }
}

// ---------------- node encoder (fp32 FFMA) ----------------------------------
__global__ void enc_nodes_kernel(const float* __restrict__ nf,
                                 const float* __restrict__ W,
                                 const float* __restrict__ b) {
    extern __shared__ float sm[];
    float* sIn = sm;
    float* sW  = sm + 64*64;
    int tid = threadIdx.x, warp = tid >> 5, lane = tid & 31;
    int rb = blockIdx.x * 64;
#pragma unroll
    for (int it = 0; it < 4; ++it) {
        int idx = tid + it*256;
        int row = idx >> 4, c4 = idx & 15;
        int r = rb + row; if (r >= Nn) r = Nn - 1;
        ((float4*)sIn)[idx] = ((const float4*)(nf + (size_t)r*64))[c4];
    }
#pragma unroll
    for (int it = 0; it < 8; ++it) {
        int idx = tid + it*256;
        ((float4*)sW)[idx] = ((const float4*)W)[idx];
    }
    __syncthreads();
    float acc[8][4];
#pragma unroll
    for (int i = 0; i < 8; ++i) { acc[i][0]=acc[i][1]=acc[i][2]=acc[i][3]=0.f; }
#pragma unroll 8
    for (int k = 0; k < 64; ++k) {
        float4 w = ((float4*)(sW + k*128))[lane];
#pragma unroll
        for (int i = 0; i < 8; ++i) {
            float a = sIn[(warp*8 + i)*64 + k];
            acc[i][0] = fmaf(a, w.x, acc[i][0]);
            acc[i][1] = fmaf(a, w.y, acc[i][1]);
            acc[i][2] = fmaf(a, w.z, acc[i][2]);
            acc[i][3] = fmaf(a, w.w, acc[i][3]);
        }
    }
    float4 bb = ((const float4*)b)[lane];
#pragma unroll
    for (int i = 0; i < 8; ++i) {
        int r = rb + warp*8 + i;
        if (r < Nn) {
            float4 v = make_float4(acc[i][0]+bb.x, acc[i][1]+bb.y,
                                   acc[i][2]+bb.z, acc[i][3]+bb.w);
            ((float4*)(g_x + (size_t)r*128))[lane] = v;
            *(uint2*)(g_xbf + (size_t)r*128 + lane*4) =
                make_uint2(packbf(v.x, v.y), packbf(v.z, v.w));
        }
    }
}

// --------- per-layer node precompute + agg zero -----------------------------
// xa = x@W1a + cong*wc + b1 + (be@W1e) ; xb = x@W1b
__global__ void __launch_bounds__(256,2) node_pre_mma(const float* __restrict__ cong,
                                 const float* __restrict__ w1l,
                                 const float* __restrict__ b1,
                                 int layer) {
    extern __shared__ __nv_bfloat16 smx[];
    __nv_bfloat16* sA = smx;
    __nv_bfloat16* sW = smx + 128*LDS;
    const __nv_bfloat16* wb = g_w + (size_t)layer*WL;
    int tid = threadIdx.x, warp = tid >> 5, lane = tid & 31;
    int rb = blockIdx.x * 128;
    float4 z4 = make_float4(0.f,0.f,0.f,0.f);
#pragma unroll
    for (int it = 0; it < 16; ++it) {
        int idx = tid + it*256;
        int row = idx >> 5, c4 = idx & 31;
        int r = rb + row;
        if (r < Nn) ((float4*)(g_agg + (size_t)r*128))[c4] = z4;
    }
#pragma unroll
    for (int it = 0; it < 8; ++it) {
        int idx = tid + it*256; int row = idx >> 4, c = idx & 15;
        int r = rb + row; if (r >= Nn) r = Nn - 1;
        *(uint4*)(sA + row*LDS + c*8) = __ldg((const uint4*)(g_xbf + (size_t)r*128) + c);
    }
    float acc[16][4];
#pragma unroll
    for (int j = 0; j < 16; ++j) { acc[j][0]=acc[j][1]=acc[j][2]=acc[j][3]=0.f; }
#pragma unroll 1
    for (int ph = 0; ph < 2; ++ph) {
        __syncthreads();
        load_wbf(wb + (size_t)ph*B_EL, sW, tid);
        __syncthreads();
        mma_gemm128(sA, sW, acc, warp, lane);
    }
    int g = lane >> 2, t4 = lane & 3;
    int r0 = rb + warp*16 + g, r1 = r0 + 8;
    float c0 = cong[r0 < Nn ? r0 : Nn-1];
    float c1 = cong[r1 < Nn ? r1 : Nn-1];
#pragma unroll
    for (int j = 0; j < 16; ++j) {
        int col = j*8 + t4*2;
        float2 wc = *(const float2*)(w1l + 384*128 + col);
        float2 bb = *(const float2*)(b1 + col);
        float2 be = *(const float2*)(g_be + layer*128 + col);
        bb.x += be.x; bb.y += be.y;
        if (r0 < Nn)
            *(unsigned*)(g_xa + (size_t)r0*128 + col) =
                packbf(acc[j][0] + c0*wc.x + bb.x, acc[j][1] + c0*wc.y + bb.y);
        if (r1 < Nn)
            *(unsigned*)(g_xa + (size_t)r1*128 + col) =
                packbf(acc[j][2] + c1*wc.x + bb.x, acc[j][3] + c1*wc.y + bb.y);
        acc[j][0]=acc[j][1]=acc[j][2]=acc[j][3]=0.f;
    }
#pragma unroll 1
    for (int ph = 0; ph < 2; ++ph) {
        __syncthreads();
        load_wbf(wb + (size_t)(2+ph)*B_EL, sW, tid);
        __syncthreads();
        mma_gemm128(sA, sW, acc, warp, lane);
    }
#pragma unroll
    for (int j = 0; j < 16; ++j) {
        int col = j*8 + t4*2;
        if (r0 < Nn)
            *(unsigned*)(g_xb + (size_t)r0*128 + col) = packbf(acc[j][0], acc[j][1]);
        if (r1 < Nn)
            *(unsigned*)(g_xb + (size_t)r1*128 + col) = packbf(acc[j][2], acc[j][3]);
    }
}

__global__ void zero_red_kernel() { if (threadIdx.x < 128) g_red[threadIdx.x] = 0.f; }

// ------- persistent edge kernel: K=32 composite GEMM + h1 scatter -----------
// h1 = relu(ef@Wce + xa[src] + xb[dst]); agg[dst] += h1    (3 CTAs/SM)
__global__ void __launch_bounds__(256,3) edge_persist_kernel(
                                const int* __restrict__ eidx, int layer) {
    extern __shared__ __nv_bfloat16 smx[];
    __nv_bfloat16* sEF = smx;                       // 128 x LDSE (ef bf16)
    __nv_bfloat16* sW  = smx + 128*LDSE;            // 64 x LDS (hi 32, lo 32)
    __nv_bfloat16* sG  = smx + 128*LDSE + 64*LDS;   // 128 x LDS (gather)
    __shared__ int sSe[128], sDe[128];
    int tid = threadIdx.x, w = tid >> 5, lane = tid & 31;

    // composite weight hi/lo: 64 rows x 16 uint4 = 1024 uint4
#pragma unroll
    for (int it = 0; it < 4; ++it) {
        int idx = tid + it*256;
        int row = idx >> 4, c = idx & 15;
        *(uint4*)(sW + row*LDS + c*8) =
            __ldg((const uint4*)(g_wce + (size_t)layer*8192) + idx);
    }
    __syncthreads();

    int g = lane >> 2, t4 = lane & 3;

    for (int t = blockIdx.x; t < Ee/128; t += gridDim.x) {
        size_t eb = (size_t)t * 128;
        __syncwarp();                         // prev tile fully consumed (warp-local)
        if (lane < 16) sSe[w*16 + lane] = eidx[eb + w*16 + lane];
        else           sDe[w*16 + lane - 16] = eidx[(size_t)Ee + eb + w*16 + lane - 16];
        // own 16 ef rows (32 bf16 each): 64 uint4 per warp, 2 per lane
#pragma unroll
        for (int k = 0; k < 2; ++k) {
            int idx = lane + k*32; int lr = idx >> 2, c = idx & 3;
            *(uint4*)(sEF + (w*16 + lr)*LDSE + c*8) =
                __ldg((const uint4*)(g_efbf + (eb + w*16 + lr)*32) + c);
        }
        __syncwarp();
        float acc[16][4];
#pragma unroll
        for (int j = 0; j < 16; ++j) { acc[j][0]=acc[j][1]=acc[j][2]=acc[j][3]=0.f; }
        // GEMM: K=32, hi + lo parts
        unsigned aB = sptr(sEF + (w*16 + (lane & 15))*LDSE + (lane >> 4)*8);
#pragma unroll
        for (int part = 0; part < 2; ++part) {
            unsigned bB = sptr(sW + (part*32 + (lane & 15))*LDS + (lane >> 4)*8);
#pragma unroll
            for (int kk = 0; kk < 2; ++kk) {
                unsigned a0,a1,a2,a3;
                ldsmA(aB + kk*32, a0,a1,a2,a3);
#pragma unroll
                for (int jp = 0; jp < 8; ++jp) {
                    unsigned b0,b1,b2,b3;
                    ldsmBT(bB + kk*(16*LDS*2) + jp*32, b0,b1,b2,b3);
                    mma_bf16(acc[2*jp],   a0,a1,a2,a3, b0,b1);
                    mma_bf16(acc[2*jp+1], a0,a1,a2,a3, b2,b3);
                }
            }
        }
        // gather xa[src]+xb[dst] -> own sG rows
#pragma unroll
        for (int k = 0; k < 8; ++k) {
            int idx = lane + k*32; int lr = idx >> 4, c = idx & 15;
            int row = w*16 + lr;
            uint4 a = __ldg((const uint4*)(g_xa + (size_t)sSe[row]*128) + c);
            uint4 b = __ldg((const uint4*)(g_xb + (size_t)sDe[row]*128) + c);
            uint4 r;
            ((__nv_bfloat162&)r.x) = __hadd2(((__nv_bfloat162&)a.x), ((__nv_bfloat162&)b.x));
            ((__nv_bfloat162&)r.y) = __hadd2(((__nv_bfloat162&)a.y), ((__nv_bfloat162&)b.y));
            ((__nv_bfloat162&)r.z) = __hadd2(((__nv_bfloat162&)a.z), ((__nv_bfloat162&)b.z));
            ((__nv_bfloat162&)r.w) = __hadd2(((__nv_bfloat162&)a.w), ((__nv_bfloat162&)b.w));
            *(uint4*)(sG + row*LDS + c*8) = r;
        }
        __syncwarp();
        // h1 = relu(acc + gather); shuffle-assemble 4 cols; red4 scatter
        int dst0 = sDe[w*16 + g], dst1 = sDe[w*16 + g + 8];
#pragma unroll
        for (int j = 0; j < 16; ++j) {
            int col = j*8 + t4*2;
            int row0 = w*16 + g, row1 = row0 + 8;
            float2 g0 = unpackbf(*(unsigned*)(sG + row0*LDS + col));
            float2 g1 = unpackbf(*(unsigned*)(sG + row1*LDS + col));
            float v0 = fmaxf(acc[j][0] + g0.x, 0.f);
            float v1 = fmaxf(acc[j][1] + g0.y, 0.f);
            float w0 = fmaxf(acc[j][2] + g1.x, 0.f);
            float w1 = fmaxf(acc[j][3] + g1.y, 0.f);
            float pv0 = __shfl_xor_sync(0xffffffffu, v0, 1);
            float pv1 = __shfl_xor_sync(0xffffffffu, v1, 1);
            float pw0 = __shfl_xor_sync(0xffffffffu, w0, 1);
            float pw1 = __shfl_xor_sync(0xffffffffu, w1, 1);
            int colb = j*8 + ((t4 & 2) ? 4 : 0);
            if ((t4 & 1) == 0) {
                red4(g_agg + (size_t)dst0*128 + colb, v0, v1, pv0, pv1);
            } else {
                red4(g_agg + (size_t)dst1*128 + colb, pw0, pw1, w0, w1);
            }
        }
    }
}

// ------- update (mma): x = LN(x + MLP2(relu(x@U1a + aggH@C + deg*v + ub1))) -
__global__ void __launch_bounds__(256,2) update_mma(const float* __restrict__ ub1,
                               const float* __restrict__ ub2,
                               const float* __restrict__ lw,
                               const float* __restrict__ lb,
                               int layer) {
    extern __shared__ __nv_bfloat16 smx[];
    __nv_bfloat16* sA = smx;
    __nv_bfloat16* sW = smx + 128*LDS;
    const __nv_bfloat16* wb = g_w + (size_t)layer*WL;
    int tid = threadIdx.x, warp = tid >> 5, lane = tid & 31;
    int rb = blockIdx.x * 128;
    float acc[16][4];
#pragma unroll
    for (int j = 0; j < 16; ++j) { acc[j][0]=acc[j][1]=acc[j][2]=acc[j][3]=0.f; }
#pragma unroll 1
    for (int kc = 0; kc < 2; ++kc) {
        __syncthreads();
        if (kc == 0) {
#pragma unroll
            for (int it = 0; it < 8; ++it) {
                int idx = tid + it*256; int row = idx >> 4, c = idx & 15;
                int r = rb + row; if (r >= Nn) r = Nn - 1;
                *(uint4*)(sA + row*LDS + c*8) =
                    __ldg((const uint4*)(g_xbf + (size_t)r*128) + c);
            }
        } else {
#pragma unroll
            for (int it = 0; it < 16; ++it) {
                int idx = tid + it*256; int row = idx >> 5, c4 = idx & 31;
                int r = rb + row; if (r >= Nn) r = Nn - 1;
                float4 w = __ldg((const float4*)(g_agg + (size_t)r*128) + c4);
                *(uint2*)(sA + row*LDS + c4*4) =
                    make_uint2(packbf(w.x, w.y), packbf(w.z, w.w));
            }
        }
#pragma unroll 1
        for (int ph = 0; ph < 2; ++ph) {
            __syncthreads();
            const __nv_bfloat16* ws = (kc == 0)
                ? wb + (size_t)(8 + ph*2)*B_EL
                : g_wc + (size_t)layer*2*B_EL + (size_t)ph*B_EL;
            load_wbf(ws, sW, tid);
            __syncthreads();
            mma_gemm128(sA, sW, acc, warp, lane);
        }
    }
    __syncthreads();
    int g = lane >> 2, t4 = lane & 3;
    int r0 = rb + warp*16 + g, r1 = r0 + 8;
    int r0c = r0 < Nn ? r0 : Nn-1, r1c = r1 < Nn ? r1 : Nn-1;
    float dg0 = g_deg[r0c], dg1 = g_deg[r1c];
#pragma unroll
    for (int j = 0; j < 16; ++j) {
        int col = j*8 + t4*2;
        float2 bb = *(const float2*)(ub1 + col);
        float2 vv = *(const float2*)(g_v + layer*128 + col);
#pragma unroll
        for (int rr = 0; rr < 2; ++rr) {
            int row = warp*16 + g + rr*8;
            float dg = rr ? dg1 : dg0;
            float h0 = fmaxf(acc[j][2*rr]   + bb.x + dg*vv.x, 0.f);
            float h1 = fmaxf(acc[j][2*rr+1] + bb.y + dg*vv.y, 0.f);
            *(unsigned*)(sA + row*LDS + col) = packbf(h0, h1);
            acc[j][2*rr] = 0.f; acc[j][2*rr+1] = 0.f;
        }
    }
#pragma unroll 1
    for (int ph = 0; ph < 2; ++ph) {
        __syncthreads();
        load_wbf(wb + (size_t)(12 + ph)*B_EL, sW, tid);
        __syncthreads();
        mma_gemm128(sA, sW, acc, warp, lane);
    }
    float s0 = 0.f, s1 = 0.f;
#pragma unroll
    for (int j = 0; j < 16; ++j) {
        int col = j*8 + t4*2;
        float2 bb = *(const float2*)(ub2 + col);
        float2 x0 = *(const float2*)(g_x + (size_t)r0c*128 + col);
        float2 x1 = *(const float2*)(g_x + (size_t)r1c*128 + col);
        acc[j][0] += x0.x + bb.x;  acc[j][1] += x0.y + bb.y;
        acc[j][2] += x1.x + bb.x;  acc[j][3] += x1.y + bb.y;
        s0 += acc[j][0] + acc[j][1];
        s1 += acc[j][2] + acc[j][3];
    }
    s0 += __shfl_xor_sync(0xffffffffu, s0, 1);
    s0 += __shfl_xor_sync(0xffffffffu, s0, 2);
    s1 += __shfl_xor_sync(0xffffffffu, s1, 1);
    s1 += __shfl_xor_sync(0xffffffffu, s1, 2);
    float mu0 = s0 * (1.f/128.f), mu1 = s1 * (1.f/128.f);
    float q0 = 0.f, q1 = 0.f;
#pragma unroll
    for (int j = 0; j < 16; ++j) {
        float d0 = acc[j][0]-mu0, d1 = acc[j][1]-mu0;
        float d2 = acc[j][2]-mu1, d3 = acc[j][3]-mu1;
        q0 += d0*d0 + d1*d1;
        q1 += d2*d2 + d3*d3;
    }
    q0 += __shfl_xor_sync(0xffffffffu, q0, 1);
    q0 += __shfl_xor_sync(0xffffffffu, q0, 2);
    q1 += __shfl_xor_sync(0xffffffffu, q1, 1);
    q1 += __shfl_xor_sync(0xffffffffu, q1, 2);
    float rstd0 = rsqrtf(q0 * (1.f/128.f) + 1e-5f);
    float rstd1 = rsqrtf(q1 * (1.f/128.f) + 1e-5f);
#pragma unroll
    for (int j = 0; j < 16; ++j) {
        int col = j*8 + t4*2;
        float2 lw2 = *(const float2*)(lw + col);
        float2 lb2 = *(const float2*)(lb + col);
        if (r0 < Nn) {
            float o0 = (acc[j][0]-mu0)*rstd0*lw2.x + lb2.x;
            float o1 = (acc[j][1]-mu0)*rstd0*lw2.y + lb2.y;
            *(float2*)(g_x + (size_t)r0*128 + col) = make_float2(o0, o1);
            *(unsigned*)(g_xbf + (size_t)r0*128 + col) = packbf(o0, o1);
        }
        if (r1 < Nn) {
            float o2 = (acc[j][2]-mu1)*rstd1*lw2.x + lb2.x;
            float o3 = (acc[j][3]-mu1)*rstd1*lw2.y + lb2.y;
            *(float2*)(g_x + (size_t)r1*128 + col) = make_float2(o2, o3);
            *(unsigned*)(g_xbf + (size_t)r1*128 + col) = packbf(o2, o3);
        }
    }
}

// ---------------- column-sum reduce + readout -------------------------------
__global__ void reduce_kernel() {
    int j = threadIdx.x;
    int chunk = (Nn + gridDim.x - 1) / gridDim.x;
    int r0 = blockIdx.x * chunk;
    int r1 = r0 + chunk; if (r1 > Nn) r1 = Nn;
    float s = 0.f;
    for (int r = r0; r < r1; ++r) s += g_x[(size_t)r*128 + j];
    atomicAdd(&g_red[j], s);
}

__global__ void final_kernel(const void* __restrict__ maskp,
                             const float* __restrict__ uw1, const float* __restrict__ ub1f,
                             const float* __restrict__ uw2, const float* __restrict__ ub2f,
                             const float* __restrict__ rw1, const float* __restrict__ rb1,
                             const float* __restrict__ rw2, const float* __restrict__ rb2,
                             const float* __restrict__ rw3, const float* __restrict__ rb3,
                             float* __restrict__ out) {
    __shared__ float sge[128], s1[128], s2[128];
    __shared__ int c1s, c2s;
    __shared__ float sufs;
    int j = threadIdx.x;
    if (j == 0) { c1s = 0; c2s = 0; sufs = 0.f; }
    __syncthreads();
    const unsigned char* mb = (const unsigned char*)maskp;
    int c1 = 0, c2 = 0;
    for (int i = j; i < Nn; i += 128) {
        unsigned char v = mb[i];
        if (v) { if ((i & 3) == 0) c1++; else c2++; }
    }
    atomicAdd(&c1s, c1); atomicAdd(&c2s, c2);
    __syncthreads();
    float s = 0.f;
    if (c2s == 0) {
        const int* mi = (const int*)maskp;
        for (int i = j; i < Nn; i += 128) s += (mi[i] != 0) ? 1.f : 0.f;
    } else if (c1s == 0) {
        const float* mf = (const float*)maskp;
        for (int i = j; i < Nn; i += 128) s += mf[i];
    } else {
        for (int i = j; i < Nn; i += 128) s += mb[i] ? 1.f : 0.f;
    }
    atomicAdd(&sufs, s);
    sge[j] = g_red[j] * (1.f/(float)Nn);
    __syncthreads();
    float uf = sufs * (1.f/(float)Nn);
    s1[j] = fmaxf(uf * uw1[j] + ub1f[j], 0.f);
    __syncthreads();
    float t = ub2f[j];
    for (int k = 0; k < 128; ++k) t = fmaf(s1[k], uw2[k*128 + j], t);
    s2[j] = t;
    __syncthreads();
    float h = rb1[j];
    for (int k = 0; k < 128; ++k) h = fmaf(sge[k], rw1[k*128 + j], h);
    for (int k = 0; k < 128; ++k) h = fmaf(s2[k], rw1[(128 + k)*128 + j], h);
    s1[j] = fmaxf(h, 0.f);
    __syncthreads();
    if (j < 64) {
        float gv = rb2[j];
        for (int k = 0; k < 128; ++k) gv = fmaf(s1[k], rw2[k*64 + j], gv);
        s2[j] = fmaxf(gv, 0.f);
    }
    __syncthreads();
    if (j == 0) {
        float o = rb3[0];
        for (int k = 0; k < 64; ++k) o = fmaf(s2[k], rw3[k], o);
        out[0] = 1.f / (1.f + expf(-o));
    }
}

// ---------------- launch -----------------------------------------------------
extern "C" void kernel_launch(void* const* d_in, const int* in_sizes, int n_in,
                              void* d_out, int out_size) {
    const float* nf        = (const float*)d_in[0];
    const float* ef        = (const float*)d_in[1];
    const float* cong      = (const float*)d_in[2];
    const int*   eidx      = (const int*)d_in[3];
    const void*  mask      = d_in[4];
    const float* enc_node_w = (const float*)d_in[5];
    const float* enc_node_b = (const float*)d_in[6];
    const float* enc_edge_w = (const float*)d_in[7];
    const float* enc_edge_b = (const float*)d_in[8];
    const float* msg_w1 = (const float*)d_in[9];
    const float* msg_b1 = (const float*)d_in[10];
    const float* msg_w2 = (const float*)d_in[11];
    const float* msg_b2 = (const float*)d_in[12];
    const float* upd_w1 = (const float*)d_in[13];
    const float* upd_b1 = (const float*)d_in[14];
    const float* upd_w2 = (const float*)d_in[15];
    const float* upd_b2 = (const float*)d_in[16];
    const float* ln_w   = (const float*)d_in[17];
    const float* ln_b   = (const float*)d_in[18];
    const float* unr_w1 = (const float*)d_in[19];
    const float* unr_b1 = (const float*)d_in[20];
    const float* unr_w2 = (const float*)d_in[21];
    const float* unr_b2 = (const float*)d_in[22];
    const float* ro_w1  = (const float*)d_in[23];
    const float* ro_b1  = (const float*)d_in[24];
    const float* ro_w2  = (const float*)d_in[25];
    const float* ro_b2  = (const float*)d_in[26];
    const float* ro_w3  = (const float*)d_in[27];
    const float* ro_b3  = (const float*)d_in[28];
    float* out = (float*)d_out;

    const int SM_ENC_N = (64*64 + 64*128) * 4;
    const int SM_MMA2  = 2 * 128 * LDS * 2;                      // 69632 B
    const int SM_EDGE  = (128*LDSE + 64*LDS + 128*LDS) * 2;      // 62464 B

    cudaFuncSetAttribute(enc_nodes_kernel,    cudaFuncAttributeMaxDynamicSharedMemorySize, SM_ENC_N);
    cudaFuncSetAttribute(node_pre_mma,        cudaFuncAttributeMaxDynamicSharedMemorySize, SM_MMA2);
    cudaFuncSetAttribute(edge_persist_kernel, cudaFuncAttributeMaxDynamicSharedMemorySize, SM_EDGE);
    cudaFuncSetAttribute(update_mma,          cudaFuncAttributeMaxDynamicSharedMemorySize, SM_MMA2);

    const int SPLIT_TOTAL = 4*7*B_EL;
    const int ENC_N_BLOCKS = (Nn + 63) / 64;
    const int NODE_BLOCKS  = (Nn + 127) / 128;

    // launch order arranged so ncu slot 6 = edge_persist_kernel
    split_all_kernel<<<(SPLIT_TOTAL + 255)/256, 256>>>(
        msg_w1, msg_w2, upd_w1, upd_w2);                               // 1
    efconv_kernel<<<2048, 256>>>(ef);                                  // 2
    enc_nodes_kernel<<<ENC_N_BLOCKS, 256, SM_ENC_N>>>(nf, enc_node_w, enc_node_b); // 3
    wce_prec_kernel<<<(4*32*128 + 255)/256, 256>>>(msg_w1, enc_edge_w, enc_edge_b); // 4
    node_pre_mma<<<NODE_BLOCKS, 256, SM_MMA2>>>(cong, msg_w1, msg_b1, 0); // 5
    edge_persist_kernel<<<444, 256, SM_EDGE>>>(eidx, 0);               // 6  <- ncu
    zero_deg_kernel<<<(Nn + 1023)/1024, 1024>>>();                     // 7
    deg_accum_kernel<<<(Ee + 255)/256, 256>>>(eidx);                   // 8
    wprec_kernel<<<(4*B_EL + 255)/256, 256>>>(msg_w2, upd_w1, msg_b2); // 9
    update_mma<<<NODE_BLOCKS, 256, SM_MMA2>>>(upd_b1, upd_b2, ln_w, ln_b, 0); // 10

    for (int l = 1; l < 4; ++l) {
        node_pre_mma<<<NODE_BLOCKS, 256, SM_MMA2>>>(
            cong, msg_w1 + (size_t)l*385*128, msg_b1 + (size_t)l*128, l);
        edge_persist_kernel<<<444, 256, SM_EDGE>>>(eidx, l);
        update_mma<<<NODE_BLOCKS, 256, SM_MMA2>>>(
            upd_b1 + (size_t)l*128, upd_b2 + (size_t)l*128,
            ln_w + (size_t)l*128, ln_b + (size_t)l*128, l);
    }

    zero_red_kernel<<<1, 128>>>();
    reduce_kernel<<<250, 128>>>();
    final_kernel<<<1, 128>>>(mask, unr_w1, unr_b1, unr_w2, unr_b2,
                             ro_w1, ro_b1, ro_w2, ro_b2, ro_w3, ro_b3, out);
}

// round 13
// speedup vs baseline: 1.2595x; 1.0716x over previous
#include <cuda_runtime.h>
#include <cuda_bf16.h>
#include <math.h>

#define Nn 50000
#define Ee 800000
#define LDS 136       // smem row stride (bf16 elems) for 128-wide tiles
#define LDSE 40       // smem row stride for 32-wide ef tiles
#define B_EL 16384    // 128*128
#define WL   229376   // per-layer elems in g_w (14 * B_EL)

// ---------------- scratch (device globals; no allocation allowed) -----------
__device__ float          g_x  [(size_t)Nn*128];
__device__ __nv_bfloat16  g_xbf[(size_t)Nn*128];
__device__ __nv_bfloat16  g_xa [(size_t)Nn*128];
__device__ __nv_bfloat16  g_xb [(size_t)Nn*128];
__device__ float          g_agg[(size_t)Nn*128];   // aggregated h1 (fp32)
__device__ __nv_bfloat16  g_efbf[(size_t)Ee*32];   // ef in bf16
__device__ float          g_red[128];
__device__ float          g_deg[Nn];
__device__ float          g_v  [4*128];            // b2 @ U1b per layer
__device__ float          g_be [4*128];            // be @ W1e per layer
__device__ __nv_bfloat16  g_w[(size_t)4*WL];
__device__ __nv_bfloat16  g_wc [(size_t)4*2*B_EL]; // (W2@U1b) hi/lo per layer
__device__ __nv_bfloat16  g_wce[(size_t)4*2*4096]; // (We@W1e) hi/lo per layer [32,128]

// ---------------- mma helpers ------------------------------------------------
__device__ __forceinline__ unsigned sptr(const void* p){
    return (unsigned)__cvta_generic_to_shared((void*)p);
}
__device__ __forceinline__ void ldsmA(unsigned a, unsigned &r0, unsigned &r1,
                                      unsigned &r2, unsigned &r3){
    asm volatile("ldmatrix.sync.aligned.m8n8.x4.shared.b16 {%0,%1,%2,%3},[%4];"
        : "=r"(r0),"=r"(r1),"=r"(r2),"=r"(r3) : "r"(a));
}
__device__ __forceinline__ void ldsmBT(unsigned a, unsigned &r0, unsigned &r1,
                                       unsigned &r2, unsigned &r3){
    asm volatile("ldmatrix.sync.aligned.m8n8.x4.trans.shared.b16 {%0,%1,%2,%3},[%4];"
        : "=r"(r0),"=r"(r1),"=r"(r2),"=r"(r3) : "r"(a));
}
__device__ __forceinline__ void mma_bf16(float* c, unsigned a0, unsigned a1,
                                         unsigned a2, unsigned a3,
                                         unsigned b0, unsigned b1){
    asm volatile("mma.sync.aligned.m16n8k16.row.col.f32.bf16.bf16.f32 "
        "{%0,%1,%2,%3},{%4,%5,%6,%7},{%8,%9},{%0,%1,%2,%3};"
        : "+f"(c[0]),"+f"(c[1]),"+f"(c[2]),"+f"(c[3])
        : "r"(a0),"r"(a1),"r"(a2),"r"(a3),"r"(b0),"r"(b1));
}
__device__ __forceinline__ unsigned packbf(float a, float b){
    __nv_bfloat162 h = __floats2bfloat162_rn(a, b);
    return *(unsigned*)&h;
}
__device__ __forceinline__ float2 unpackbf(unsigned u){
    __nv_bfloat162 h = *(__nv_bfloat162*)&u;
    return make_float2(__bfloat162float(h.x), __bfloat162float(h.y));
}
__device__ __forceinline__ void red4(float* p, float a, float b, float c, float d){
    asm volatile("red.global.add.v4.f32 [%0], {%1,%2,%3,%4};"
        :: "l"(p), "f"(a), "f"(b), "f"(c), "f"(d) : "memory");
}
__device__ __forceinline__ void pref_l1(const void* p){
    asm volatile("prefetch.global.L1 [%0];" :: "l"(p));
}

// -------- fused weight pre-split (ONE launch): hi=bf16(w), lo=bf16(w-hi) ----
__global__ void split_all_kernel(const float* __restrict__ msg_w1,
                                 const float* __restrict__ msg_w2,
                                 const float* __restrict__ upd_w1,
                                 const float* __restrict__ upd_w2){
    const int PER_L = 7*B_EL;
    int i = blockIdx.x*blockDim.x + threadIdx.x;
    if (i >= 4*PER_L) return;
    float w; size_t hid; size_t lstep;
    int l = i / PER_L, k = i % PER_L;
    size_t base = (size_t)l*WL;
    if (k < 3*B_EL) {                       // W1a, W1b, W1e
        w = msg_w1[(size_t)l*385*128 + k];
        int blk = k / B_EL, off = k % B_EL;
        hid = base + (size_t)(2*blk)*B_EL + off; lstep = B_EL;
    } else if (k < 4*B_EL) {                // W2
        int off = k - 3*B_EL;
        w = msg_w2[(size_t)l*B_EL + off];
        hid = base + (size_t)6*B_EL + off; lstep = B_EL;
    } else if (k < 6*B_EL) {                // U1 (2 blocks)
        int off = k - 4*B_EL;
        w = upd_w1[(size_t)l*2*B_EL + off];
        hid = base + (size_t)8*B_EL + off; lstep = 2*B_EL;
    } else {                                // U2
        int off = k - 6*B_EL;
        w = upd_w2[(size_t)l*B_EL + off];
        hid = base + (size_t)12*B_EL + off; lstep = B_EL;
    }
    __nv_bfloat16 h = __float2bfloat16(w);
    g_w[hid] = h;
    g_w[hid + lstep] = __float2bfloat16(w - __bfloat162float(h));
}

// -------- ef -> bf16 (once) -------------------------------------------------
__global__ void efconv_kernel(const float* __restrict__ ef){
    size_t i = (size_t)blockIdx.x*blockDim.x + threadIdx.x;
    size_t n = (size_t)Ee*32;
    for (; i < n; i += (size_t)gridDim.x*blockDim.x)
        g_efbf[i] = __float2bfloat16(ef[i]);
}

// -------- composite edge weight: Wce = We@W1e (hi/lo), g_be = be@W1e --------
__global__ void wce_prec_kernel(const float* __restrict__ msg_w1,
                                const float* __restrict__ enc_edge_w,
                                const float* __restrict__ enc_edge_b){
    int idx = blockIdx.x*blockDim.x + threadIdx.x;
    if (idx >= 4*32*128) return;
    int l = idx >> 12; int ij = idx & 4095;
    int i = ij >> 7, j = ij & 127;
    const float* W1e = msg_w1 + (size_t)l*385*128 + 256*128;
    float c = 0.f;
#pragma unroll 4
    for (int k = 0; k < 128; ++k)
        c = fmaf(enc_edge_w[i*128 + k], W1e[k*128 + j], c);
    __nv_bfloat16 h = __float2bfloat16(c);
    g_wce[(size_t)l*8192 + ij] = h;
    g_wce[(size_t)l*8192 + 4096 + ij] = __float2bfloat16(c - __bfloat162float(h));
    if (i == 0) {
        float v = 0.f;
#pragma unroll 4
        for (int k = 0; k < 128; ++k)
            v = fmaf(enc_edge_b[k], W1e[k*128 + j], v);
        g_be[l*128 + j] = v;
    }
}

// -------- composite update weight: C = W2@U1b, v = b2@U1b -------------------
__global__ void wprec_kernel(const float* __restrict__ msg_w2,
                             const float* __restrict__ upd_w1,
                             const float* __restrict__ msg_b2){
    int idx = blockIdx.x*blockDim.x + threadIdx.x;
    if (idx >= 4*B_EL) return;
    int l = idx >> 14; int ij = idx & 16383;
    int i = ij >> 7, j = ij & 127;
    const float* W2  = msg_w2 + (size_t)l*B_EL;
    const float* U1b = upd_w1 + (size_t)l*2*B_EL + B_EL;
    float c = 0.f;
#pragma unroll 4
    for (int k = 0; k < 128; ++k)
        c = fmaf(W2[i*128 + k], U1b[k*128 + j], c);
    __nv_bfloat16 h = __float2bfloat16(c);
    g_wc[(size_t)l*2*B_EL + ij] = h;
    g_wc[(size_t)l*2*B_EL + B_EL + ij] = __float2bfloat16(c - __bfloat162float(h));
    if (i == 0) {
        float v = 0.f;
#pragma unroll 4
        for (int k = 0; k < 128; ++k)
            v = fmaf(msg_b2[l*128 + k], U1b[k*128 + j], v);
        g_v[l*128 + j] = v;
    }
}

// -------- degree (once) -----------------------------------------------------
__global__ void zero_deg_kernel(){
    int i = blockIdx.x*blockDim.x + threadIdx.x;
    if (i < Nn) g_deg[i] = 0.f;
}
__global__ void deg_accum_kernel(const int* __restrict__ eidx){
    int i = blockIdx.x*blockDim.x + threadIdx.x;
    if (i < Ee) atomicAdd(&g_deg[eidx[(size_t)Ee + i]], 1.f);
}

// Load dense bf16 [128][128] weight into SMEM [128][LDS].  256 threads.
__device__ __forceinline__ void load_wbf(const __nv_bfloat16* __restrict__ Wd,
                                         __nv_bfloat16* sW, int tid){
#pragma unroll
    for (int it = 0; it < 8; ++it){
        int idx = tid + it*256;
        int row = idx >> 4, c = idx & 15;
        *(uint4*)(sW + row*LDS + c*8) = __ldg((const uint4*)Wd + idx);
    }
}

// Warp-level 16x128 @ 128x128 mma accumulate. Warp w owns rows w*16..w*16+15.
__device__ __forceinline__ void mma_gemm128(const __nv_bfloat16* sA,
                                            const __nv_bfloat16* sW,
                                            float acc[16][4], int warp, int lane){
    unsigned aB = sptr(sA + (warp*16 + (lane & 15))*LDS + (lane >> 4)*8);
    unsigned bB = sptr(sW + (lane & 15)*LDS + (lane >> 4)*8);
#pragma unroll
    for (int kk = 0; kk < 8; ++kk){
        unsigned a0,a1,a2,a3;
        ldsmA(aB + kk*32, a0,a1,a2,a3);
#pragma unroll
        for (int jp = 0; jp < 8; ++jp){
            unsigned b0,b1,b2,b3;
            ldsmBT(bB + kk*(16*LDS*2) + jp*32, b0,b1,b2,b3);
            mma_bf16(acc[2*jp],   a0,a1,a2,a3, b0,b1);
            mma_bf16(acc[2*jp+1], a0,a1,a2,a3, b2,b3);
        }
    }
}

// ---------------- node encoder (fp32 FFMA) ----------------------------------
__global__ void enc_nodes_kernel(const float* __restrict__ nf,
                                 const float* __restrict__ W,
                                 const float* __restrict__ b) {
    extern __shared__ float sm[];
    float* sIn = sm;
    float* sW  = sm + 64*64;
    int tid = threadIdx.x, warp = tid >> 5, lane = tid & 31;
    int rb = blockIdx.x * 64;
#pragma unroll
    for (int it = 0; it < 4; ++it) {
        int idx = tid + it*256;
        int row = idx >> 4, c4 = idx & 15;
        int r = rb + row; if (r >= Nn) r = Nn - 1;
        ((float4*)sIn)[idx] = ((const float4*)(nf + (size_t)r*64))[c4];
    }
#pragma unroll
    for (int it = 0; it < 8; ++it) {
        int idx = tid + it*256;
        ((float4*)sW)[idx] = ((const float4*)W)[idx];
    }
    __syncthreads();
    float acc[8][4];
#pragma unroll
    for (int i = 0; i < 8; ++i) { acc[i][0]=acc[i][1]=acc[i][2]=acc[i][3]=0.f; }
#pragma unroll 8
    for (int k = 0; k < 64; ++k) {
        float4 w = ((float4*)(sW + k*128))[lane];
#pragma unroll
        for (int i = 0; i < 8; ++i) {
            float a = sIn[(warp*8 + i)*64 + k];
            acc[i][0] = fmaf(a, w.x, acc[i][0]);
            acc[i][1] = fmaf(a, w.y, acc[i][1]);
            acc[i][2] = fmaf(a, w.z, acc[i][2]);
            acc[i][3] = fmaf(a, w.w, acc[i][3]);
        }
    }
    float4 bb = ((const float4*)b)[lane];
#pragma unroll
    for (int i = 0; i < 8; ++i) {
        int r = rb + warp*8 + i;
        if (r < Nn) {
            float4 v = make_float4(acc[i][0]+bb.x, acc[i][1]+bb.y,
                                   acc[i][2]+bb.z, acc[i][3]+bb.w);
            ((float4*)(g_x + (size_t)r*128))[lane] = v;
            *(uint2*)(g_xbf + (size_t)r*128 + lane*4) =
                make_uint2(packbf(v.x, v.y), packbf(v.z, v.w));
        }
    }
}

// --------- xa/xb epilogue + GEMMs from an sA tile already in SMEM -----------
// (shared by node_pre_mma and the fused update kernel)
__device__ __forceinline__ void node_pre_body(
        __nv_bfloat16* sA, __nv_bfloat16* sW,
        const float* cong, const float* w1l, const float* b1,
        const __nv_bfloat16* wb, int layer, int rb,
        int tid, int warp, int lane){
    float acc[16][4];
#pragma unroll
    for (int j = 0; j < 16; ++j) { acc[j][0]=acc[j][1]=acc[j][2]=acc[j][3]=0.f; }
#pragma unroll 1
    for (int ph = 0; ph < 2; ++ph) {
        __syncthreads();
        load_wbf(wb + (size_t)ph*B_EL, sW, tid);
        __syncthreads();
        mma_gemm128(sA, sW, acc, warp, lane);
    }
    int g = lane >> 2, t4 = lane & 3;
    int r0 = rb + warp*16 + g, r1 = r0 + 8;
    float c0 = cong[r0 < Nn ? r0 : Nn-1];
    float c1 = cong[r1 < Nn ? r1 : Nn-1];
#pragma unroll
    for (int j = 0; j < 16; ++j) {
        int col = j*8 + t4*2;
        float2 wc = *(const float2*)(w1l + 384*128 + col);
        float2 bb = *(const float2*)(b1 + col);
        float2 be = *(const float2*)(g_be + layer*128 + col);
        bb.x += be.x; bb.y += be.y;
        if (r0 < Nn)
            *(unsigned*)(g_xa + (size_t)r0*128 + col) =
                packbf(acc[j][0] + c0*wc.x + bb.x, acc[j][1] + c0*wc.y + bb.y);
        if (r1 < Nn)
            *(unsigned*)(g_xa + (size_t)r1*128 + col) =
                packbf(acc[j][2] + c1*wc.x + bb.x, acc[j][3] + c1*wc.y + bb.y);
        acc[j][0]=acc[j][1]=acc[j][2]=acc[j][3]=0.f;
    }
#pragma unroll 1
    for (int ph = 0; ph < 2; ++ph) {
        __syncthreads();
        load_wbf(wb + (size_t)(2+ph)*B_EL, sW, tid);
        __syncthreads();
        mma_gemm128(sA, sW, acc, warp, lane);
    }
#pragma unroll
    for (int j = 0; j < 16; ++j) {
        int col = j*8 + t4*2;
        if (r0 < Nn)
            *(unsigned*)(g_xb + (size_t)r0*128 + col) = packbf(acc[j][0], acc[j][1]);
        if (r1 < Nn)
            *(unsigned*)(g_xb + (size_t)r1*128 + col) = packbf(acc[j][2], acc[j][3]);
    }
}

// --------- layer-0 node precompute + agg zero -------------------------------
__global__ void __launch_bounds__(256,2) node_pre_mma(const float* __restrict__ cong,
                                 const float* __restrict__ w1l,
                                 const float* __restrict__ b1,
                                 int layer) {
    extern __shared__ __nv_bfloat16 smx[];
    __nv_bfloat16* sA = smx;
    __nv_bfloat16* sW = smx + 128*LDS;
    const __nv_bfloat16* wb = g_w + (size_t)layer*WL;
    int tid = threadIdx.x, warp = tid >> 5, lane = tid & 31;
    int rb = blockIdx.x * 128;
    float4 z4 = make_float4(0.f,0.f,0.f,0.f);
#pragma unroll
    for (int it = 0; it < 16; ++it) {
        int idx = tid + it*256;
        int row = idx >> 5, c4 = idx & 31;
        int r = rb + row;
        if (r < Nn) ((float4*)(g_agg + (size_t)r*128))[c4] = z4;
    }
#pragma unroll
    for (int it = 0; it < 8; ++it) {
        int idx = tid + it*256; int row = idx >> 4, c = idx & 15;
        int r = rb + row; if (r >= Nn) r = Nn - 1;
        *(uint4*)(sA + row*LDS + c*8) = __ldg((const uint4*)(g_xbf + (size_t)r*128) + c);
    }
    node_pre_body(sA, sW, cong, w1l, b1, wb, layer, rb, tid, warp, lane);
}

__global__ void zero_red_kernel() { if (threadIdx.x < 128) g_red[threadIdx.x] = 0.f; }

// ------- persistent edge kernel: K=32 composite GEMM + h1 scatter -----------
// h1 = relu(ef@Wce + xa[src] + xb[dst]); agg[dst] += h1   (2 CTAs/SM, R10 cfg)
__global__ void __launch_bounds__(256,2) edge_persist_kernel(
                                const int* __restrict__ eidx, int layer) {
    extern __shared__ __nv_bfloat16 smx[];
    __nv_bfloat16* sEF = smx;                       // 128 x LDSE (ef bf16)
    __nv_bfloat16* sW  = smx + 128*LDSE;            // 64 x LDS (hi 32, lo 32)
    __nv_bfloat16* sG  = smx + 128*LDSE + 64*LDS;   // 128 x LDS (gather)
    __shared__ int sSe[128], sDe[128];
    int tid = threadIdx.x, w = tid >> 5, lane = tid & 31;

#pragma unroll
    for (int it = 0; it < 4; ++it) {
        int idx = tid + it*256;
        int row = idx >> 4, c = idx & 15;
        *(uint4*)(sW + row*LDS + c*8) =
            __ldg((const uint4*)(g_wce + (size_t)layer*8192) + idx);
    }
    __syncthreads();

    int g = lane >> 2, t4 = lane & 3;

    for (int t = blockIdx.x; t < Ee/128; t += gridDim.x) {
        size_t eb = (size_t)t * 128;
        __syncwarp();                         // prev tile fully consumed (warp-local)
        if (lane < 16) sSe[w*16 + lane] = eidx[eb + w*16 + lane];
        else           sDe[w*16 + lane - 16] = eidx[(size_t)Ee + eb + w*16 + lane - 16];
        __syncwarp();
        // L1-prefetch gather lines (own 16 rows; 2 x 128B lines per row)
        {
            int lr = lane & 15, row = w*16 + lr;
            if (lane < 16) {
                const char* p = (const char*)(g_xa + (size_t)sSe[row]*128);
                pref_l1(p); pref_l1(p + 128);
            } else {
                const char* p = (const char*)(g_xb + (size_t)sDe[row]*128);
                pref_l1(p); pref_l1(p + 128);
            }
        }
        // own 16 ef rows (32 bf16 each): 64 uint4 per warp, 2 per lane
#pragma unroll
        for (int k = 0; k < 2; ++k) {
            int idx = lane + k*32; int lr = idx >> 2, c = idx & 3;
            *(uint4*)(sEF + (w*16 + lr)*LDSE + c*8) =
                __ldg((const uint4*)(g_efbf + (eb + w*16 + lr)*32) + c);
        }
        __syncwarp();
        float acc[16][4];
#pragma unroll
        for (int j = 0; j < 16; ++j) { acc[j][0]=acc[j][1]=acc[j][2]=acc[j][3]=0.f; }
        // GEMM: K=32, hi + lo parts
        unsigned aB = sptr(sEF + (w*16 + (lane & 15))*LDSE + (lane >> 4)*8);
#pragma unroll
        for (int part = 0; part < 2; ++part) {
            unsigned bB = sptr(sW + (part*32 + (lane & 15))*LDS + (lane >> 4)*8);
#pragma unroll
            for (int kk = 0; kk < 2; ++kk) {
                unsigned a0,a1,a2,a3;
                ldsmA(aB + kk*32, a0,a1,a2,a3);
#pragma unroll
                for (int jp = 0; jp < 8; ++jp) {
                    unsigned b0,b1,b2,b3;
                    ldsmBT(bB + kk*(16*LDS*2) + jp*32, b0,b1,b2,b3);
                    mma_bf16(acc[2*jp],   a0,a1,a2,a3, b0,b1);
                    mma_bf16(acc[2*jp+1], a0,a1,a2,a3, b2,b3);
                }
            }
        }
        // gather xa[src]+xb[dst] -> own sG rows (should now hit L1)
#pragma unroll
        for (int k = 0; k < 8; ++k) {
            int idx = lane + k*32; int lr = idx >> 4, c = idx & 15;
            int row = w*16 + lr;
            uint4 a = __ldg((const uint4*)(g_xa + (size_t)sSe[row]*128) + c);
            uint4 b = __ldg((const uint4*)(g_xb + (size_t)sDe[row]*128) + c);
            uint4 r;
            ((__nv_bfloat162&)r.x) = __hadd2(((__nv_bfloat162&)a.x), ((__nv_bfloat162&)b.x));
            ((__nv_bfloat162&)r.y) = __hadd2(((__nv_bfloat162&)a.y), ((__nv_bfloat162&)b.y));
            ((__nv_bfloat162&)r.z) = __hadd2(((__nv_bfloat162&)a.z), ((__nv_bfloat162&)b.z));
            ((__nv_bfloat162&)r.w) = __hadd2(((__nv_bfloat162&)a.w), ((__nv_bfloat162&)b.w));
            *(uint4*)(sG + row*LDS + c*8) = r;
        }
        __syncwarp();
        // h1 = relu(acc + gather); shuffle-assemble 4 cols; red4 scatter
        int dst0 = sDe[w*16 + g], dst1 = sDe[w*16 + g + 8];
#pragma unroll
        for (int j = 0; j < 16; ++j) {
            int col = j*8 + t4*2;
            int row0 = w*16 + g, row1 = row0 + 8;
            float2 g0 = unpackbf(*(unsigned*)(sG + row0*LDS + col));
            float2 g1 = unpackbf(*(unsigned*)(sG + row1*LDS + col));
            float v0 = fmaxf(acc[j][0] + g0.x, 0.f);
            float v1 = fmaxf(acc[j][1] + g0.y, 0.f);
            float w0 = fmaxf(acc[j][2] + g1.x, 0.f);
            float w1 = fmaxf(acc[j][3] + g1.y, 0.f);
            float pv0 = __shfl_xor_sync(0xffffffffu, v0, 1);
            float pv1 = __shfl_xor_sync(0xffffffffu, v1, 1);
            float pw0 = __shfl_xor_sync(0xffffffffu, w0, 1);
            float pw1 = __shfl_xor_sync(0xffffffffu, w1, 1);
            int colb = j*8 + ((t4 & 2) ? 4 : 0);
            if ((t4 & 1) == 0) {
                red4(g_agg + (size_t)dst0*128 + colb, v0, v1, pv0, pv1);
            } else {
                red4(g_agg + (size_t)dst1*128 + colb, pw0, pw1, w0, w1);
            }
        }
    }
}

// ------- update (mma) + fused next-layer node precompute --------------------
// x = LN(x + MLP2(relu(x@U1a + aggH@C + deg*v + ub1)));
// if has_next: xa/xb for layer+1 computed from the fresh x tile in SMEM.
__global__ void __launch_bounds__(256,2) update_mma(const float* __restrict__ ub1,
                               const float* __restrict__ ub2,
                               const float* __restrict__ lw,
                               const float* __restrict__ lb,
                               int layer,
                               const float* __restrict__ cong,
                               const float* __restrict__ w1l_next,
                               const float* __restrict__ b1_next,
                               int has_next) {
    extern __shared__ __nv_bfloat16 smx[];
    __nv_bfloat16* sA = smx;
    __nv_bfloat16* sW = smx + 128*LDS;
    const __nv_bfloat16* wb = g_w + (size_t)layer*WL;
    int tid = threadIdx.x, warp = tid >> 5, lane = tid & 31;
    int rb = blockIdx.x * 128;
    float acc[16][4];
#pragma unroll
    for (int j = 0; j < 16; ++j) { acc[j][0]=acc[j][1]=acc[j][2]=acc[j][3]=0.f; }
#pragma unroll 1
    for (int kc = 0; kc < 2; ++kc) {
        __syncthreads();
        if (kc == 0) {
#pragma unroll
            for (int it = 0; it < 8; ++it) {
                int idx = tid + it*256; int row = idx >> 4, c = idx & 15;
                int r = rb + row; if (r >= Nn) r = Nn - 1;
                *(uint4*)(sA + row*LDS + c*8) =
                    __ldg((const uint4*)(g_xbf + (size_t)r*128) + c);
            }
        } else {
#pragma unroll
            for (int it = 0; it < 16; ++it) {
                int idx = tid + it*256; int row = idx >> 5, c4 = idx & 31;
                int r = rb + row; if (r >= Nn) r = Nn - 1;
                float4 w = __ldg((const float4*)(g_agg + (size_t)r*128) + c4);
                *(uint2*)(sA + row*LDS + c4*4) =
                    make_uint2(packbf(w.x, w.y), packbf(w.z, w.w));
            }
        }
#pragma unroll 1
        for (int ph = 0; ph < 2; ++ph) {
            __syncthreads();
            const __nv_bfloat16* ws = (kc == 0)
                ? wb + (size_t)(8 + ph*2)*B_EL
                : g_wc + (size_t)layer*2*B_EL + (size_t)ph*B_EL;
            load_wbf(ws, sW, tid);
            __syncthreads();
            mma_gemm128(sA, sW, acc, warp, lane);
        }
    }
    __syncthreads();
    int g = lane >> 2, t4 = lane & 3;
    int r0 = rb + warp*16 + g, r1 = r0 + 8;
    int r0c = r0 < Nn ? r0 : Nn-1, r1c = r1 < Nn ? r1 : Nn-1;
    float dg0 = g_deg[r0c], dg1 = g_deg[r1c];
#pragma unroll
    for (int j = 0; j < 16; ++j) {
        int col = j*8 + t4*2;
        float2 bb = *(const float2*)(ub1 + col);
        float2 vv = *(const float2*)(g_v + layer*128 + col);
#pragma unroll
        for (int rr = 0; rr < 2; ++rr) {
            int row = warp*16 + g + rr*8;
            float dg = rr ? dg1 : dg0;
            float h0 = fmaxf(acc[j][2*rr]   + bb.x + dg*vv.x, 0.f);
            float h1 = fmaxf(acc[j][2*rr+1] + bb.y + dg*vv.y, 0.f);
            *(unsigned*)(sA + row*LDS + col) = packbf(h0, h1);
            acc[j][2*rr] = 0.f; acc[j][2*rr+1] = 0.f;
        }
    }
#pragma unroll 1
    for (int ph = 0; ph < 2; ++ph) {
        __syncthreads();
        load_wbf(wb + (size_t)(12 + ph)*B_EL, sW, tid);
        __syncthreads();
        mma_gemm128(sA, sW, acc, warp, lane);
    }
    float s0 = 0.f, s1 = 0.f;
#pragma unroll
    for (int j = 0; j < 16; ++j) {
        int col = j*8 + t4*2;
        float2 bb = *(const float2*)(ub2 + col);
        float2 x0 = *(const float2*)(g_x + (size_t)r0c*128 + col);
        float2 x1 = *(const float2*)(g_x + (size_t)r1c*128 + col);
        acc[j][0] += x0.x + bb.x;  acc[j][1] += x0.y + bb.y;
        acc[j][2] += x1.x + bb.x;  acc[j][3] += x1.y + bb.y;
        s0 += acc[j][0] + acc[j][1];
        s1 += acc[j][2] + acc[j][3];
    }
    s0 += __shfl_xor_sync(0xffffffffu, s0, 1);
    s0 += __shfl_xor_sync(0xffffffffu, s0, 2);
    s1 += __shfl_xor_sync(0xffffffffu, s1, 1);
    s1 += __shfl_xor_sync(0xffffffffu, s1, 2);
    float mu0 = s0 * (1.f/128.f), mu1 = s1 * (1.f/128.f);
    float q0 = 0.f, q1 = 0.f;
#pragma unroll
    for (int j = 0; j < 16; ++j) {
        float d0 = acc[j][0]-mu0, d1 = acc[j][1]-mu0;
        float d2 = acc[j][2]-mu1, d3 = acc[j][3]-mu1;
        q0 += d0*d0 + d1*d1;
        q1 += d2*d2 + d3*d3;
    }
    q0 += __shfl_xor_sync(0xffffffffu, q0, 1);
    q0 += __shfl_xor_sync(0xffffffffu, q0, 2);
    q1 += __shfl_xor_sync(0xffffffffu, q1, 1);
    q1 += __shfl_xor_sync(0xffffffffu, q1, 2);
    float rstd0 = rsqrtf(q0 * (1.f/128.f) + 1e-5f);
    float rstd1 = rsqrtf(q1 * (1.f/128.f) + 1e-5f);
    __syncwarp();   // own-warp ldmatrix of sA (h1) done before overwrite
#pragma unroll
    for (int j = 0; j < 16; ++j) {
        int col = j*8 + t4*2;
        float2 lw2 = *(const float2*)(lw + col);
        float2 lb2 = *(const float2*)(lb + col);
        float o0 = (acc[j][0]-mu0)*rstd0*lw2.x + lb2.x;
        float o1 = (acc[j][1]-mu0)*rstd0*lw2.y + lb2.y;
        float o2 = (acc[j][2]-mu1)*rstd1*lw2.x + lb2.x;
        float o3 = (acc[j][3]-mu1)*rstd1*lw2.y + lb2.y;
        if (r0 < Nn) {
            *(float2*)(g_x + (size_t)r0*128 + col) = make_float2(o0, o1);
            *(unsigned*)(g_xbf + (size_t)r0*128 + col) = packbf(o0, o1);
        }
        if (r1 < Nn) {
            *(float2*)(g_x + (size_t)r1*128 + col) = make_float2(o2, o3);
            *(unsigned*)(g_xbf + (size_t)r1*128 + col) = packbf(o2, o3);
        }
        int row0 = warp*16 + g, row1 = row0 + 8;
        *(unsigned*)(sA + row0*LDS + col) = packbf(o0, o1);
        *(unsigned*)(sA + row1*LDS + col) = packbf(o2, o3);
    }
    if (!has_next) return;
    // zero agg rows for the next layer
    float4 z4 = make_float4(0.f,0.f,0.f,0.f);
#pragma unroll
    for (int it = 0; it < 16; ++it) {
        int idx = tid + it*256;
        int row = idx >> 5, c4 = idx & 31;
        int r = rb + row;
        if (r < Nn) ((float4*)(g_agg + (size_t)r*128))[c4] = z4;
    }
    node_pre_body(sA, sW, cong, w1l_next, b1_next,
                  g_w + (size_t)(layer+1)*WL, layer+1, rb, tid, warp, lane);
}

// ---------------- column-sum reduce + readout -------------------------------
__global__ void reduce_kernel() {
    int j = threadIdx.x;
    int chunk = (Nn + gridDim.x - 1) / gridDim.x;
    int r0 = blockIdx.x * chunk;
    int r1 = r0 + chunk; if (r1 > Nn) r1 = Nn;
    float s = 0.f;
    for (int r = r0; r < r1; ++r) s += g_x[(size_t)r*128 + j];
    atomicAdd(&g_red[j], s);
}

__global__ void final_kernel(const void* __restrict__ maskp,
                             const float* __restrict__ uw1, const float* __restrict__ ub1f,
                             const float* __restrict__ uw2, const float* __restrict__ ub2f,
                             const float* __restrict__ rw1, const float* __restrict__ rb1,
                             const float* __restrict__ rw2, const float* __restrict__ rb2,
                             const float* __restrict__ rw3, const float* __restrict__ rb3,
                             float* __restrict__ out) {
    __shared__ float sge[128], s1[128], s2[128];
    __shared__ int c1s, c2s;
    __shared__ float sufs;
    int j = threadIdx.x;
    if (j == 0) { c1s = 0; c2s = 0; sufs = 0.f; }
    __syncthreads();
    const unsigned char* mb = (const unsigned char*)maskp;
    int c1 = 0, c2 = 0;
    for (int i = j; i < Nn; i += 128) {
        unsigned char v = mb[i];
        if (v) { if ((i & 3) == 0) c1++; else c2++; }
    }
    atomicAdd(&c1s, c1); atomicAdd(&c2s, c2);
    __syncthreads();
    float s = 0.f;
    if (c2s == 0) {
        const int* mi = (const int*)maskp;
        for (int i = j; i < Nn; i += 128) s += (mi[i] != 0) ? 1.f : 0.f;
    } else if (c1s == 0) {
        const float* mf = (const float*)maskp;
        for (int i = j; i < Nn; i += 128) s += mf[i];
    } else {
        for (int i = j; i < Nn; i += 128) s += mb[i] ? 1.f : 0.f;
    }
    atomicAdd(&sufs, s);
    sge[j] = g_red[j] * (1.f/(float)Nn);
    __syncthreads();
    float uf = sufs * (1.f/(float)Nn);
    s1[j] = fmaxf(uf * uw1[j] + ub1f[j], 0.f);
    __syncthreads();
    float t = ub2f[j];
    for (int k = 0; k < 128; ++k) t = fmaf(s1[k], uw2[k*128 + j], t);
    s2[j] = t;
    __syncthreads();
    float h = rb1[j];
    for (int k = 0; k < 128; ++k) h = fmaf(sge[k], rw1[k*128 + j], h);
    for (int k = 0; k < 128; ++k) h = fmaf(s2[k], rw1[(128 + k)*128 + j], h);
    s1[j] = fmaxf(h, 0.f);
    __syncthreads();
    if (j < 64) {
        float gv = rb2[j];
        for (int k = 0; k < 128; ++k) gv = fmaf(s1[k], rw2[k*64 + j], gv);
        s2[j] = fmaxf(gv, 0.f);
    }
    __syncthreads();
    if (j == 0) {
        float o = rb3[0];
        for (int k = 0; k < 64; ++k) o = fmaf(s2[k], rw3[k], o);
        out[0] = 1.f / (1.f + expf(-o));
    }
}

// ---------------- launch -----------------------------------------------------
extern "C" void kernel_launch(void* const* d_in, const int* in_sizes, int n_in,
                              void* d_out, int out_size) {
    const float* nf        = (const float*)d_in[0];
    const float* ef        = (const float*)d_in[1];
    const float* cong      = (const float*)d_in[2];
    const int*   eidx      = (const int*)d_in[3];
    const void*  mask      = d_in[4];
    const float* enc_node_w = (const float*)d_in[5];
    const float* enc_node_b = (const float*)d_in[6];
    const float* enc_edge_w = (const float*)d_in[7];
    const float* enc_edge_b = (const float*)d_in[8];
    const float* msg_w1 = (const float*)d_in[9];
    const float* msg_b1 = (const float*)d_in[10];
    const float* msg_w2 = (const float*)d_in[11];
    const float* msg_b2 = (const float*)d_in[12];
    const float* upd_w1 = (const float*)d_in[13];
    const float* upd_b1 = (const float*)d_in[14];
    const float* upd_w2 = (const float*)d_in[15];
    const float* upd_b2 = (const float*)d_in[16];
    const float* ln_w   = (const float*)d_in[17];
    const float* ln_b   = (const float*)d_in[18];
    const float* unr_w1 = (const float*)d_in[19];
    const float* unr_b1 = (const float*)d_in[20];
    const float* unr_w2 = (const float*)d_in[21];
    const float* unr_b2 = (const float*)d_in[22];
    const float* ro_w1  = (const float*)d_in[23];
    const float* ro_b1  = (const float*)d_in[24];
    const float* ro_w2  = (const float*)d_in[25];
    const float* ro_b2  = (const float*)d_in[26];
    const float* ro_w3  = (const float*)d_in[27];
    const float* ro_b3  = (const float*)d_in[28];
    float* out = (float*)d_out;

    const int SM_ENC_N = (64*64 + 64*128) * 4;
    const int SM_MMA2  = 2 * 128 * LDS * 2;                      // 69632 B
    const int SM_EDGE  = (128*LDSE + 64*LDS + 128*LDS) * 2;      // 62464 B

    cudaFuncSetAttribute(enc_nodes_kernel,    cudaFuncAttributeMaxDynamicSharedMemorySize, SM_ENC_N);
    cudaFuncSetAttribute(node_pre_mma,        cudaFuncAttributeMaxDynamicSharedMemorySize, SM_MMA2);
    cudaFuncSetAttribute(edge_persist_kernel, cudaFuncAttributeMaxDynamicSharedMemorySize, SM_EDGE);
    cudaFuncSetAttribute(update_mma,          cudaFuncAttributeMaxDynamicSharedMemorySize, SM_MMA2);

    const int SPLIT_TOTAL = 4*7*B_EL;
    const int ENC_N_BLOCKS = (Nn + 63) / 64;
    const int NODE_BLOCKS  = (Nn + 127) / 128;

    split_all_kernel<<<(SPLIT_TOTAL + 255)/256, 256>>>(
        msg_w1, msg_w2, upd_w1, upd_w2);                               // 1
    efconv_kernel<<<2048, 256>>>(ef);                                  // 2
    enc_nodes_kernel<<<ENC_N_BLOCKS, 256, SM_ENC_N>>>(nf, enc_node_w, enc_node_b); // 3
    wce_prec_kernel<<<(4*32*128 + 255)/256, 256>>>(msg_w1, enc_edge_w, enc_edge_b); // 4
    node_pre_mma<<<NODE_BLOCKS, 256, SM_MMA2>>>(cong, msg_w1, msg_b1, 0); // 5
    edge_persist_kernel<<<296, 256, SM_EDGE>>>(eidx, 0);               // 6  <- ncu
    zero_deg_kernel<<<(Nn + 1023)/1024, 1024>>>();                     // 7
    deg_accum_kernel<<<(Ee + 255)/256, 256>>>(eidx);                   // 8
    wprec_kernel<<<(4*B_EL + 255)/256, 256>>>(msg_w2, upd_w1, msg_b2); // 9

    for (int l = 0; l < 4; ++l) {
        if (l > 0)
            edge_persist_kernel<<<296, 256, SM_EDGE>>>(eidx, l);
        int hn = (l < 3) ? 1 : 0;
        update_mma<<<NODE_BLOCKS, 256, SM_MMA2>>>(
            upd_b1 + (size_t)l*128, upd_b2 + (size_t)l*128,
            ln_w + (size_t)l*128, ln_b + (size_t)l*128, l,
            cong,
            msg_w1 + (size_t)(l+1 < 4 ? l+1 : l)*385*128,
            msg_b1 + (size_t)(l+1 < 4 ? l+1 : l)*128,
            hn);
    }

    zero_red_kernel<<<1, 128>>>();
    reduce_kernel<<<250, 128>>>();
    final_kernel<<<1, 128>>>(mask, unr_w1, unr_b1, unr_w2, unr_b2,
                             ro_w1, ro_b1, ro_w2, ro_b2, ro_w3, ro_b3, out);
}

// round 14
// speedup vs baseline: 1.2794x; 1.0158x over previous
#include <cuda_runtime.h>
#include <cuda_bf16.h>
#include <math.h>

#define Nn 50000
#define Ee 800000
#define LDS 136       // smem row stride (bf16 elems) for 128-wide tiles
#define LDSE 40       // smem row stride for 32-wide ef tiles
#define B_EL 16384    // 128*128
#define WL   229376   // per-layer elems in g_w (14 * B_EL)

// ---------------- scratch (device globals; no allocation allowed) -----------
__device__ float          g_x  [(size_t)Nn*128];
__device__ __nv_bfloat16  g_xbf[(size_t)Nn*128];
__device__ __nv_bfloat16  g_xa [(size_t)Nn*128];
__device__ __nv_bfloat16  g_xb [(size_t)Nn*128];
__device__ float          g_agg[(size_t)Nn*128];   // aggregated h1 (fp32)
__device__ __nv_bfloat16  g_efbf[(size_t)Ee*32];   // ef in bf16
__device__ float          g_red[128];
__device__ float          g_deg[Nn];
__device__ float          g_v  [4*128];            // b2 @ U1b per layer
__device__ float          g_be [4*128];            // be @ W1e per layer
__device__ __nv_bfloat16  g_w[(size_t)4*WL];
__device__ __nv_bfloat16  g_wc [(size_t)4*2*B_EL]; // (W2@U1b) hi/lo per layer
__device__ __nv_bfloat16  g_wce[(size_t)4*4096];   // (We@W1e) hi per layer [32,128]

// ---------------- mma helpers ------------------------------------------------
__device__ __forceinline__ unsigned sptr(const void* p){
    return (unsigned)__cvta_generic_to_shared((void*)p);
}
__device__ __forceinline__ void ldsmA(unsigned a, unsigned &r0, unsigned &r1,
                                      unsigned &r2, unsigned &r3){
    asm volatile("ldmatrix.sync.aligned.m8n8.x4.shared.b16 {%0,%1,%2,%3},[%4];"
        : "=r"(r0),"=r"(r1),"=r"(r2),"=r"(r3) : "r"(a));
}
__device__ __forceinline__ void ldsmBT(unsigned a, unsigned &r0, unsigned &r1,
                                       unsigned &r2, unsigned &r3){
    asm volatile("ldmatrix.sync.aligned.m8n8.x4.trans.shared.b16 {%0,%1,%2,%3},[%4];"
        : "=r"(r0),"=r"(r1),"=r"(r2),"=r"(r3) : "r"(a));
}
__device__ __forceinline__ void mma_bf16(float* c, unsigned a0, unsigned a1,
                                         unsigned a2, unsigned a3,
                                         unsigned b0, unsigned b1){
    asm volatile("mma.sync.aligned.m16n8k16.row.col.f32.bf16.bf16.f32 "
        "{%0,%1,%2,%3},{%4,%5,%6,%7},{%8,%9},{%0,%1,%2,%3};"
        : "+f"(c[0]),"+f"(c[1]),"+f"(c[2]),"+f"(c[3])
        : "r"(a0),"r"(a1),"r"(a2),"r"(a3),"r"(b0),"r"(b1));
}
__device__ __forceinline__ unsigned packbf(float a, float b){
    __nv_bfloat162 h = __floats2bfloat162_rn(a, b);
    return *(unsigned*)&h;
}
__device__ __forceinline__ float2 unpackbf(unsigned u){
    __nv_bfloat162 h = *(__nv_bfloat162*)&u;
    return make_float2(__bfloat162float(h.x), __bfloat162float(h.y));
}
__device__ __forceinline__ void red4(float* p, float a, float b, float c, float d){
    asm volatile("red.global.add.v4.f32 [%0], {%1,%2,%3,%4};"
        :: "l"(p), "f"(a), "f"(b), "f"(c), "f"(d) : "memory");
}
__device__ __forceinline__ void pref_l1(const void* p){
    asm volatile("prefetch.global.L1 [%0];" :: "l"(p));
}

// -------- fused weight pre-split (ONE launch): hi=bf16(w), lo=bf16(w-hi) ----
__global__ void split_all_kernel(const float* __restrict__ msg_w1,
                                 const float* __restrict__ msg_w2,
                                 const float* __restrict__ upd_w1,
                                 const float* __restrict__ upd_w2){
    const int PER_L = 7*B_EL;
    int i = blockIdx.x*blockDim.x + threadIdx.x;
    if (i >= 4*PER_L) return;
    float w; size_t hid; size_t lstep;
    int l = i / PER_L, k = i % PER_L;
    size_t base = (size_t)l*WL;
    if (k < 3*B_EL) {                       // W1a, W1b, W1e
        w = msg_w1[(size_t)l*385*128 + k];
        int blk = k / B_EL, off = k % B_EL;
        hid = base + (size_t)(2*blk)*B_EL + off; lstep = B_EL;
    } else if (k < 4*B_EL) {                // W2
        int off = k - 3*B_EL;
        w = msg_w2[(size_t)l*B_EL + off];
        hid = base + (size_t)6*B_EL + off; lstep = B_EL;
    } else if (k < 6*B_EL) {                // U1 (2 blocks)
        int off = k - 4*B_EL;
        w = upd_w1[(size_t)l*2*B_EL + off];
        hid = base + (size_t)8*B_EL + off; lstep = 2*B_EL;
    } else {                                // U2
        int off = k - 6*B_EL;
        w = upd_w2[(size_t)l*B_EL + off];
        hid = base + (size_t)12*B_EL + off; lstep = B_EL;
    }
    __nv_bfloat16 h = __float2bfloat16(w);
    g_w[hid] = h;
    g_w[hid + lstep] = __float2bfloat16(w - __bfloat162float(h));
}

// -------- ef -> bf16 (once) -------------------------------------------------
__global__ void efconv_kernel(const float* __restrict__ ef){
    size_t i = (size_t)blockIdx.x*blockDim.x + threadIdx.x;
    size_t n = (size_t)Ee*32;
    for (; i < n; i += (size_t)gridDim.x*blockDim.x)
        g_efbf[i] = __float2bfloat16(ef[i]);
}

// -------- composite edge weight: Wce = We@W1e (hi only), g_be = be@W1e ------
__global__ void wce_prec_kernel(const float* __restrict__ msg_w1,
                                const float* __restrict__ enc_edge_w,
                                const float* __restrict__ enc_edge_b){
    int idx = blockIdx.x*blockDim.x + threadIdx.x;
    if (idx >= 4*32*128) return;
    int l = idx >> 12; int ij = idx & 4095;
    int i = ij >> 7, j = ij & 127;
    const float* W1e = msg_w1 + (size_t)l*385*128 + 256*128;
    float c = 0.f;
#pragma unroll 4
    for (int k = 0; k < 128; ++k)
        c = fmaf(enc_edge_w[i*128 + k], W1e[k*128 + j], c);
    g_wce[(size_t)l*4096 + ij] = __float2bfloat16(c);
    if (i == 0) {
        float v = 0.f;
#pragma unroll 4
        for (int k = 0; k < 128; ++k)
            v = fmaf(enc_edge_b[k], W1e[k*128 + j], v);
        g_be[l*128 + j] = v;
    }
}

// -------- composite update weight: C = W2@U1b, v = b2@U1b -------------------
__global__ void wprec_kernel(const float* __restrict__ msg_w2,
                             const float* __restrict__ upd_w1,
                             const float* __restrict__ msg_b2){
    int idx = blockIdx.x*blockDim.x + threadIdx.x;
    if (idx >= 4*B_EL) return;
    int l = idx >> 14; int ij = idx & 16383;
    int i = ij >> 7, j = ij & 127;
    const float* W2  = msg_w2 + (size_t)l*B_EL;
    const float* U1b = upd_w1 + (size_t)l*2*B_EL + B_EL;
    float c = 0.f;
#pragma unroll 4
    for (int k = 0; k < 128; ++k)
        c = fmaf(W2[i*128 + k], U1b[k*128 + j], c);
    __nv_bfloat16 h = __float2bfloat16(c);
    g_wc[(size_t)l*2*B_EL + ij] = h;
    g_wc[(size_t)l*2*B_EL + B_EL + ij] = __float2bfloat16(c - __bfloat162float(h));
    if (i == 0) {
        float v = 0.f;
#pragma unroll 4
        for (int k = 0; k < 128; ++k)
            v = fmaf(msg_b2[l*128 + k], U1b[k*128 + j], v);
        g_v[l*128 + j] = v;
    }
}

// -------- degree (once) -----------------------------------------------------
__global__ void zero_deg_kernel(){
    int i = blockIdx.x*blockDim.x + threadIdx.x;
    if (i < Nn) g_deg[i] = 0.f;
}
__global__ void deg_accum_kernel(const int* __restrict__ eidx){
    int i = blockIdx.x*blockDim.x + threadIdx.x;
    if (i < Ee) atomicAdd(&g_deg[eidx[(size_t)Ee + i]], 1.f);
}

// Load dense bf16 [128][128] weight into SMEM [128][LDS].  256 threads.
__device__ __forceinline__ void load_wbf(const __nv_bfloat16* __restrict__ Wd,
                                         __nv_bfloat16* sW, int tid){
#pragma unroll
    for (int it = 0; it < 8; ++it){
        int idx = tid + it*256;
        int row = idx >> 4, c = idx & 15;
        *(uint4*)(sW + row*LDS + c*8) = __ldg((const uint4*)Wd + idx);
    }
}

// Warp-level 16x128 @ 128x128 mma accumulate. Warp w owns rows w*16..w*16+15.
__device__ __forceinline__ void mma_gemm128(const __nv_bfloat16* sA,
                                            const __nv_bfloat16* sW,
                                            float acc[16][4], int warp, int lane){
    unsigned aB = sptr(sA + (warp*16 + (lane & 15))*LDS + (lane >> 4)*8);
    unsigned bB = sptr(sW + (lane & 15)*LDS + (lane >> 4)*8);
#pragma unroll
    for (int kk = 0; kk < 8; ++kk){
        unsigned a0,a1,a2,a3;
        ldsmA(aB + kk*32, a0,a1,a2,a3);
#pragma unroll
        for (int jp = 0; jp < 8; ++jp){
            unsigned b0,b1,b2,b3;
            ldsmBT(bB + kk*(16*LDS*2) + jp*32, b0,b1,b2,b3);
            mma_bf16(acc[2*jp],   a0,a1,a2,a3, b0,b1);
            mma_bf16(acc[2*jp+1], a0,a1,a2,a3, b2,b3);
        }
    }
}

// ---------------- node encoder (fp32 FFMA) ----------------------------------
__global__ void enc_nodes_kernel(const float* __restrict__ nf,
                                 const float* __restrict__ W,
                                 const float* __restrict__ b) {
    extern __shared__ float sm[];
    float* sIn = sm;
    float* sW  = sm + 64*64;
    int tid = threadIdx.x, warp = tid >> 5, lane = tid & 31;
    int rb = blockIdx.x * 64;
#pragma unroll
    for (int it = 0; it < 4; ++it) {
        int idx = tid + it*256;
        int row = idx >> 4, c4 = idx & 15;
        int r = rb + row; if (r >= Nn) r = Nn - 1;
        ((float4*)sIn)[idx] = ((const float4*)(nf + (size_t)r*64))[c4];
    }
#pragma unroll
    for (int it = 0; it < 8; ++it) {
        int idx = tid + it*256;
        ((float4*)sW)[idx] = ((const float4*)W)[idx];
    }
    __syncthreads();
    float acc[8][4];
#pragma unroll
    for (int i = 0; i < 8; ++i) { acc[i][0]=acc[i][1]=acc[i][2]=acc[i][3]=0.f; }
#pragma unroll 8
    for (int k = 0; k < 64; ++k) {
        float4 w = ((float4*)(sW + k*128))[lane];
#pragma unroll
        for (int i = 0; i < 8; ++i) {
            float a = sIn[(warp*8 + i)*64 + k];
            acc[i][0] = fmaf(a, w.x, acc[i][0]);
            acc[i][1] = fmaf(a, w.y, acc[i][1]);
            acc[i][2] = fmaf(a, w.z, acc[i][2]);
            acc[i][3] = fmaf(a, w.w, acc[i][3]);
        }
    }
    float4 bb = ((const float4*)b)[lane];
#pragma unroll
    for (int i = 0; i < 8; ++i) {
        int r = rb + warp*8 + i;
        if (r < Nn) {
            float4 v = make_float4(acc[i][0]+bb.x, acc[i][1]+bb.y,
                                   acc[i][2]+bb.z, acc[i][3]+bb.w);
            ((float4*)(g_x + (size_t)r*128))[lane] = v;
            *(uint2*)(g_xbf + (size_t)r*128 + lane*4) =
                make_uint2(packbf(v.x, v.y), packbf(v.z, v.w));
        }
    }
}

// --------- xa/xb epilogue + GEMMs from an sA tile already in SMEM -----------
__device__ __forceinline__ void node_pre_body(
        __nv_bfloat16* sA, __nv_bfloat16* sW,
        const float* cong, const float* w1l, const float* b1,
        const __nv_bfloat16* wb, int layer, int rb,
        int tid, int warp, int lane){
    float acc[16][4];
#pragma unroll
    for (int j = 0; j < 16; ++j) { acc[j][0]=acc[j][1]=acc[j][2]=acc[j][3]=0.f; }
#pragma unroll 1
    for (int ph = 0; ph < 2; ++ph) {
        __syncthreads();
        load_wbf(wb + (size_t)ph*B_EL, sW, tid);
        __syncthreads();
        mma_gemm128(sA, sW, acc, warp, lane);
    }
    int g = lane >> 2, t4 = lane & 3;
    int r0 = rb + warp*16 + g, r1 = r0 + 8;
    float c0 = cong[r0 < Nn ? r0 : Nn-1];
    float c1 = cong[r1 < Nn ? r1 : Nn-1];
#pragma unroll
    for (int j = 0; j < 16; ++j) {
        int col = j*8 + t4*2;
        float2 wc = *(const float2*)(w1l + 384*128 + col);
        float2 bb = *(const float2*)(b1 + col);
        float2 be = *(const float2*)(g_be + layer*128 + col);
        bb.x += be.x; bb.y += be.y;
        if (r0 < Nn)
            *(unsigned*)(g_xa + (size_t)r0*128 + col) =
                packbf(acc[j][0] + c0*wc.x + bb.x, acc[j][1] + c0*wc.y + bb.y);
        if (r1 < Nn)
            *(unsigned*)(g_xa + (size_t)r1*128 + col) =
                packbf(acc[j][2] + c1*wc.x + bb.x, acc[j][3] + c1*wc.y + bb.y);
        acc[j][0]=acc[j][1]=acc[j][2]=acc[j][3]=0.f;
    }
#pragma unroll 1
    for (int ph = 0; ph < 2; ++ph) {
        __syncthreads();
        load_wbf(wb + (size_t)(2+ph)*B_EL, sW, tid);
        __syncthreads();
        mma_gemm128(sA, sW, acc, warp, lane);
    }
#pragma unroll
    for (int j = 0; j < 16; ++j) {
        int col = j*8 + t4*2;
        if (r0 < Nn)
            *(unsigned*)(g_xb + (size_t)r0*128 + col) = packbf(acc[j][0], acc[j][1]);
        if (r1 < Nn)
            *(unsigned*)(g_xb + (size_t)r1*128 + col) = packbf(acc[j][2], acc[j][3]);
    }
}

// --------- layer-0 node precompute + agg zero -------------------------------
__global__ void __launch_bounds__(256,2) node_pre_mma(const float* __restrict__ cong,
                                 const float* __restrict__ w1l,
                                 const float* __restrict__ b1,
                                 int layer) {
    extern __shared__ __nv_bfloat16 smx[];
    __nv_bfloat16* sA = smx;
    __nv_bfloat16* sW = smx + 128*LDS;
    const __nv_bfloat16* wb = g_w + (size_t)layer*WL;
    int tid = threadIdx.x, warp = tid >> 5, lane = tid & 31;
    int rb = blockIdx.x * 128;
    float4 z4 = make_float4(0.f,0.f,0.f,0.f);
#pragma unroll
    for (int it = 0; it < 16; ++it) {
        int idx = tid + it*256;
        int row = idx >> 5, c4 = idx & 31;
        int r = rb + row;
        if (r < Nn) ((float4*)(g_agg + (size_t)r*128))[c4] = z4;
    }
#pragma unroll
    for (int it = 0; it < 8; ++it) {
        int idx = tid + it*256; int row = idx >> 4, c = idx & 15;
        int r = rb + row; if (r >= Nn) r = Nn - 1;
        *(uint4*)(sA + row*LDS + c*8) = __ldg((const uint4*)(g_xbf + (size_t)r*128) + c);
    }
    node_pre_body(sA, sW, cong, w1l, b1, wb, layer, rb, tid, warp, lane);
}

__global__ void zero_red_kernel() { if (threadIdx.x < 128) g_red[threadIdx.x] = 0.f; }

// ------- persistent edge kernel: K=32 composite GEMM (hi-only) + h1 scatter -
__global__ void __launch_bounds__(256,2) edge_persist_kernel(
                                const int* __restrict__ eidx, int layer) {
    extern __shared__ __nv_bfloat16 smx[];
    __nv_bfloat16* sEF = smx;                       // 128 x LDSE (ef bf16)
    __nv_bfloat16* sW  = smx + 128*LDSE;            // 32 x LDS (hi only)
    __nv_bfloat16* sG  = smx + 128*LDSE + 32*LDS;   // 128 x LDS (gather)
    __shared__ int sSe[128], sDe[128];
    int tid = threadIdx.x, w = tid >> 5, lane = tid & 31;

    // composite weight hi: 32 rows x 16 uint4 = 512 uint4
#pragma unroll
    for (int it = 0; it < 2; ++it) {
        int idx = tid + it*256;
        int row = idx >> 4, c = idx & 15;
        *(uint4*)(sW + row*LDS + c*8) =
            __ldg((const uint4*)(g_wce + (size_t)layer*4096) + idx);
    }
    __syncthreads();

    int g = lane >> 2, t4 = lane & 3;

    for (int t = blockIdx.x; t < Ee/128; t += gridDim.x) {
        size_t eb = (size_t)t * 128;
        __syncwarp();                         // prev tile fully consumed (warp-local)
        if (lane < 16) sSe[w*16 + lane] = eidx[eb + w*16 + lane];
        else           sDe[w*16 + lane - 16] = eidx[(size_t)Ee + eb + w*16 + lane - 16];
        __syncwarp();
        // L1-prefetch gather lines (own 16 rows; 2 x 128B lines per row)
        {
            int lr = lane & 15, row = w*16 + lr;
            if (lane < 16) {
                const char* p = (const char*)(g_xa + (size_t)sSe[row]*128);
                pref_l1(p); pref_l1(p + 128);
            } else {
                const char* p = (const char*)(g_xb + (size_t)sDe[row]*128);
                pref_l1(p); pref_l1(p + 128);
            }
        }
        // own 16 ef rows (32 bf16 each): 64 uint4 per warp, 2 per lane
#pragma unroll
        for (int k = 0; k < 2; ++k) {
            int idx = lane + k*32; int lr = idx >> 2, c = idx & 3;
            *(uint4*)(sEF + (w*16 + lr)*LDSE + c*8) =
                __ldg((const uint4*)(g_efbf + (eb + w*16 + lr)*32) + c);
        }
        __syncwarp();
        float acc[16][4];
#pragma unroll
        for (int j = 0; j < 16; ++j) { acc[j][0]=acc[j][1]=acc[j][2]=acc[j][3]=0.f; }
        // GEMM: K=32, hi only
        unsigned aB = sptr(sEF + (w*16 + (lane & 15))*LDSE + (lane >> 4)*8);
        unsigned bB = sptr(sW + (lane & 15)*LDS + (lane >> 4)*8);
#pragma unroll
        for (int kk = 0; kk < 2; ++kk) {
            unsigned a0,a1,a2,a3;
            ldsmA(aB + kk*32, a0,a1,a2,a3);
#pragma unroll
            for (int jp = 0; jp < 8; ++jp) {
                unsigned b0,b1,b2,b3;
                ldsmBT(bB + kk*(16*LDS*2) + jp*32, b0,b1,b2,b3);
                mma_bf16(acc[2*jp],   a0,a1,a2,a3, b0,b1);
                mma_bf16(acc[2*jp+1], a0,a1,a2,a3, b2,b3);
            }
        }
        // gather xa[src]+xb[dst] -> own sG rows (should hit L1)
#pragma unroll
        for (int k = 0; k < 8; ++k) {
            int idx = lane + k*32; int lr = idx >> 4, c = idx & 15;
            int row = w*16 + lr;
            uint4 a = __ldg((const uint4*)(g_xa + (size_t)sSe[row]*128) + c);
            uint4 b = __ldg((const uint4*)(g_xb + (size_t)sDe[row]*128) + c);
            uint4 r;
            ((__nv_bfloat162&)r.x) = __hadd2(((__nv_bfloat162&)a.x), ((__nv_bfloat162&)b.x));
            ((__nv_bfloat162&)r.y) = __hadd2(((__nv_bfloat162&)a.y), ((__nv_bfloat162&)b.y));
            ((__nv_bfloat162&)r.z) = __hadd2(((__nv_bfloat162&)a.z), ((__nv_bfloat162&)b.z));
            ((__nv_bfloat162&)r.w) = __hadd2(((__nv_bfloat162&)a.w), ((__nv_bfloat162&)b.w));
            *(uint4*)(sG + row*LDS + c*8) = r;
        }
        __syncwarp();
        // h1 = relu(acc + gather); shuffle-assemble 4 cols; red4 scatter
        int dst0 = sDe[w*16 + g], dst1 = sDe[w*16 + g + 8];
#pragma unroll
        for (int j = 0; j < 16; ++j) {
            int col = j*8 + t4*2;
            int row0 = w*16 + g, row1 = row0 + 8;
            float2 g0 = unpackbf(*(unsigned*)(sG + row0*LDS + col));
            float2 g1 = unpackbf(*(unsigned*)(sG + row1*LDS + col));
            float v0 = fmaxf(acc[j][0] + g0.x, 0.f);
            float v1 = fmaxf(acc[j][1] + g0.y, 0.f);
            float w0 = fmaxf(acc[j][2] + g1.x, 0.f);
            float w1 = fmaxf(acc[j][3] + g1.y, 0.f);
            float pv0 = __shfl_xor_sync(0xffffffffu, v0, 1);
            float pv1 = __shfl_xor_sync(0xffffffffu, v1, 1);
            float pw0 = __shfl_xor_sync(0xffffffffu, w0, 1);
            float pw1 = __shfl_xor_sync(0xffffffffu, w1, 1);
            int colb = j*8 + ((t4 & 2) ? 4 : 0);
            if ((t4 & 1) == 0) {
                red4(g_agg + (size_t)dst0*128 + colb, v0, v1, pv0, pv1);
            } else {
                red4(g_agg + (size_t)dst1*128 + colb, pw0, pw1, w0, w1);
            }
        }
    }
}

// ------- update (mma) + fused next-layer node precompute --------------------
__global__ void __launch_bounds__(256,2) update_mma(const float* __restrict__ ub1,
                               const float* __restrict__ ub2,
                               const float* __restrict__ lw,
                               const float* __restrict__ lb,
                               int layer,
                               const float* __restrict__ cong,
                               const float* __restrict__ w1l_next,
                               const float* __restrict__ b1_next,
                               int has_next) {
    extern __shared__ __nv_bfloat16 smx[];
    __nv_bfloat16* sA = smx;
    __nv_bfloat16* sW = smx + 128*LDS;
    const __nv_bfloat16* wb = g_w + (size_t)layer*WL;
    int tid = threadIdx.x, warp = tid >> 5, lane = tid & 31;
    int rb = blockIdx.x * 128;
    float acc[16][4];
#pragma unroll
    for (int j = 0; j < 16; ++j) { acc[j][0]=acc[j][1]=acc[j][2]=acc[j][3]=0.f; }
#pragma unroll 1
    for (int kc = 0; kc < 2; ++kc) {
        __syncthreads();
        if (kc == 0) {
#pragma unroll
            for (int it = 0; it < 8; ++it) {
                int idx = tid + it*256; int row = idx >> 4, c = idx & 15;
                int r = rb + row; if (r >= Nn) r = Nn - 1;
                *(uint4*)(sA + row*LDS + c*8) =
                    __ldg((const uint4*)(g_xbf + (size_t)r*128) + c);
            }
        } else {
#pragma unroll
            for (int it = 0; it < 16; ++it) {
                int idx = tid + it*256; int row = idx >> 5, c4 = idx & 31;
                int r = rb + row; if (r >= Nn) r = Nn - 1;
                float4 w = __ldg((const float4*)(g_agg + (size_t)r*128) + c4);
                *(uint2*)(sA + row*LDS + c4*4) =
                    make_uint2(packbf(w.x, w.y), packbf(w.z, w.w));
            }
        }
#pragma unroll 1
        for (int ph = 0; ph < 2; ++ph) {
            __syncthreads();
            const __nv_bfloat16* ws = (kc == 0)
                ? wb + (size_t)(8 + ph*2)*B_EL
                : g_wc + (size_t)layer*2*B_EL + (size_t)ph*B_EL;
            load_wbf(ws, sW, tid);
            __syncthreads();
            mma_gemm128(sA, sW, acc, warp, lane);
        }
    }
    __syncthreads();
    int g = lane >> 2, t4 = lane & 3;
    int r0 = rb + warp*16 + g, r1 = r0 + 8;
    int r0c = r0 < Nn ? r0 : Nn-1, r1c = r1 < Nn ? r1 : Nn-1;
    float dg0 = g_deg[r0c], dg1 = g_deg[r1c];
#pragma unroll
    for (int j = 0; j < 16; ++j) {
        int col = j*8 + t4*2;
        float2 bb = *(const float2*)(ub1 + col);
        float2 vv = *(const float2*)(g_v + layer*128 + col);
#pragma unroll
        for (int rr = 0; rr < 2; ++rr) {
            int row = warp*16 + g + rr*8;
            float dg = rr ? dg1 : dg0;
            float h0 = fmaxf(acc[j][2*rr]   + bb.x + dg*vv.x, 0.f);
            float h1 = fmaxf(acc[j][2*rr+1] + bb.y + dg*vv.y, 0.f);
            *(unsigned*)(sA + row*LDS + col) = packbf(h0, h1);
            acc[j][2*rr] = 0.f; acc[j][2*rr+1] = 0.f;
        }
    }
#pragma unroll 1
    for (int ph = 0; ph < 2; ++ph) {
        __syncthreads();
        load_wbf(wb + (size_t)(12 + ph)*B_EL, sW, tid);
        __syncthreads();
        mma_gemm128(sA, sW, acc, warp, lane);
    }
    float s0 = 0.f, s1 = 0.f;
#pragma unroll
    for (int j = 0; j < 16; ++j) {
        int col = j*8 + t4*2;
        float2 bb = *(const float2*)(ub2 + col);
        float2 x0 = *(const float2*)(g_x + (size_t)r0c*128 + col);
        float2 x1 = *(const float2*)(g_x + (size_t)r1c*128 + col);
        acc[j][0] += x0.x + bb.x;  acc[j][1] += x0.y + bb.y;
        acc[j][2] += x1.x + bb.x;  acc[j][3] += x1.y + bb.y;
        s0 += acc[j][0] + acc[j][1];
        s1 += acc[j][2] + acc[j][3];
    }
    s0 += __shfl_xor_sync(0xffffffffu, s0, 1);
    s0 += __shfl_xor_sync(0xffffffffu, s0, 2);
    s1 += __shfl_xor_sync(0xffffffffu, s1, 1);
    s1 += __shfl_xor_sync(0xffffffffu, s1, 2);
    float mu0 = s0 * (1.f/128.f), mu1 = s1 * (1.f/128.f);
    float q0 = 0.f, q1 = 0.f;
#pragma unroll
    for (int j = 0; j < 16; ++j) {
        float d0 = acc[j][0]-mu0, d1 = acc[j][1]-mu0;
        float d2 = acc[j][2]-mu1, d3 = acc[j][3]-mu1;
        q0 += d0*d0 + d1*d1;
        q1 += d2*d2 + d3*d3;
    }
    q0 += __shfl_xor_sync(0xffffffffu, q0, 1);
    q0 += __shfl_xor_sync(0xffffffffu, q0, 2);
    q1 += __shfl_xor_sync(0xffffffffu, q1, 1);
    q1 += __shfl_xor_sync(0xffffffffu, q1, 2);
    float rstd0 = rsqrtf(q0 * (1.f/128.f) + 1e-5f);
    float rstd1 = rsqrtf(q1 * (1.f/128.f) + 1e-5f);
    __syncwarp();   // own-warp ldmatrix of sA (h1) done before overwrite
#pragma unroll
    for (int j = 0; j < 16; ++j) {
        int col = j*8 + t4*2;
        float2 lw2 = *(const float2*)(lw + col);
        float2 lb2 = *(const float2*)(lb + col);
        float o0 = (acc[j][0]-mu0)*rstd0*lw2.x + lb2.x;
        float o1 = (acc[j][1]-mu0)*rstd0*lw2.y + lb2.y;
        float o2 = (acc[j][2]-mu1)*rstd1*lw2.x + lb2.x;
        float o3 = (acc[j][3]-mu1)*rstd1*lw2.y + lb2.y;
        if (r0 < Nn) {
            *(float2*)(g_x + (size_t)r0*128 + col) = make_float2(o0, o1);
            *(unsigned*)(g_xbf + (size_t)r0*128 + col) = packbf(o0, o1);
        }
        if (r1 < Nn) {
            *(float2*)(g_x + (size_t)r1*128 + col) = make_float2(o2, o3);
            *(unsigned*)(g_xbf + (size_t)r1*128 + col) = packbf(o2, o3);
        }
        int row0 = warp*16 + g, row1 = row0 + 8;
        *(unsigned*)(sA + row0*LDS + col) = packbf(o0, o1);
        *(unsigned*)(sA + row1*LDS + col) = packbf(o2, o3);
    }
    if (!has_next) return;
    float4 z4 = make_float4(0.f,0.f,0.f,0.f);
#pragma unroll
    for (int it = 0; it < 16; ++it) {
        int idx = tid + it*256;
        int row = idx >> 5, c4 = idx & 31;
        int r = rb + row;
        if (r < Nn) ((float4*)(g_agg + (size_t)r*128))[c4] = z4;
    }
    node_pre_body(sA, sW, cong, w1l_next, b1_next,
                  g_w + (size_t)(layer+1)*WL, layer+1, rb, tid, warp, lane);
}

// ---------------- column-sum reduce + readout -------------------------------
__global__ void reduce_kernel() {
    int j = threadIdx.x;
    int chunk = (Nn + gridDim.x - 1) / gridDim.x;
    int r0 = blockIdx.x * chunk;
    int r1 = r0 + chunk; if (r1 > Nn) r1 = Nn;
    float s = 0.f;
    for (int r = r0; r < r1; ++r) s += g_x[(size_t)r*128 + j];
    atomicAdd(&g_red[j], s);
}

__global__ void final_kernel(const void* __restrict__ maskp,
                             const float* __restrict__ uw1, const float* __restrict__ ub1f,
                             const float* __restrict__ uw2, const float* __restrict__ ub2f,
                             const float* __restrict__ rw1, const float* __restrict__ rb1,
                             const float* __restrict__ rw2, const float* __restrict__ rb2,
                             const float* __restrict__ rw3, const float* __restrict__ rb3,
                             float* __restrict__ out) {
    __shared__ float sge[128], s1[128], s2[128];
    __shared__ int c1s, c2s;
    __shared__ float sufs;
    int j = threadIdx.x;
    if (j == 0) { c1s = 0; c2s = 0; sufs = 0.f; }
    __syncthreads();
    const unsigned char* mb = (const unsigned char*)maskp;
    int c1 = 0, c2 = 0;
    for (int i = j; i < Nn; i += 128) {
        unsigned char v = mb[i];
        if (v) { if ((i & 3) == 0) c1++; else c2++; }
    }
    atomicAdd(&c1s, c1); atomicAdd(&c2s, c2);
    __syncthreads();
    float s = 0.f;
    if (c2s == 0) {
        const int* mi = (const int*)maskp;
        for (int i = j; i < Nn; i += 128) s += (mi[i] != 0) ? 1.f : 0.f;
    } else if (c1s == 0) {
        const float* mf = (const float*)maskp;
        for (int i = j; i < Nn; i += 128) s += mf[i];
    } else {
        for (int i = j; i < Nn; i += 128) s += mb[i] ? 1.f : 0.f;
    }
    atomicAdd(&sufs, s);
    sge[j] = g_red[j] * (1.f/(float)Nn);
    __syncthreads();
    float uf = sufs * (1.f/(float)Nn);
    s1[j] = fmaxf(uf * uw1[j] + ub1f[j], 0.f);
    __syncthreads();
    float t = ub2f[j];
    for (int k = 0; k < 128; ++k) t = fmaf(s1[k], uw2[k*128 + j], t);
    s2[j] = t;
    __syncthreads();
    float h = rb1[j];
    for (int k = 0; k < 128; ++k) h = fmaf(sge[k], rw1[k*128 + j], h);
    for (int k = 0; k < 128; ++k) h = fmaf(s2[k], rw1[(128 + k)*128 + j], h);
    s1[j] = fmaxf(h, 0.f);
    __syncthreads();
    if (j < 64) {
        float gv = rb2[j];
        for (int k = 0; k < 128; ++k) gv = fmaf(s1[k], rw2[k*64 + j], gv);
        s2[j] = fmaxf(gv, 0.f);
    }
    __syncthreads();
    if (j == 0) {
        float o = rb3[0];
        for (int k = 0; k < 64; ++k) o = fmaf(s2[k], rw3[k], o);
        out[0] = 1.f / (1.f + expf(-o));
    }
}

// ---------------- launch -----------------------------------------------------
extern "C" void kernel_launch(void* const* d_in, const int* in_sizes, int n_in,
                              void* d_out, int out_size) {
    const float* nf        = (const float*)d_in[0];
    const float* ef        = (const float*)d_in[1];
    const float* cong      = (const float*)d_in[2];
    const int*   eidx      = (const int*)d_in[3];
    const void*  mask      = d_in[4];
    const float* enc_node_w = (const float*)d_in[5];
    const float* enc_node_b = (const float*)d_in[6];
    const float* enc_edge_w = (const float*)d_in[7];
    const float* enc_edge_b = (const float*)d_in[8];
    const float* msg_w1 = (const float*)d_in[9];
    const float* msg_b1 = (const float*)d_in[10];
    const float* msg_w2 = (const float*)d_in[11];
    const float* msg_b2 = (const float*)d_in[12];
    const float* upd_w1 = (const float*)d_in[13];
    const float* upd_b1 = (const float*)d_in[14];
    const float* upd_w2 = (const float*)d_in[15];
    const float* upd_b2 = (const float*)d_in[16];
    const float* ln_w   = (const float*)d_in[17];
    const float* ln_b   = (const float*)d_in[18];
    const float* unr_w1 = (const float*)d_in[19];
    const float* unr_b1 = (const float*)d_in[20];
    const float* unr_w2 = (const float*)d_in[21];
    const float* unr_b2 = (const float*)d_in[22];
    const float* ro_w1  = (const float*)d_in[23];
    const float* ro_b1  = (const float*)d_in[24];
    const float* ro_w2  = (const float*)d_in[25];
    const float* ro_b2  = (const float*)d_in[26];
    const float* ro_w3  = (const float*)d_in[27];
    const float* ro_b3  = (const float*)d_in[28];
    float* out = (float*)d_out;

    const int SM_ENC_N = (64*64 + 64*128) * 4;
    const int SM_MMA2  = 2 * 128 * LDS * 2;                      // 69632 B
    const int SM_EDGE  = (128*LDSE + 32*LDS + 128*LDS) * 2;      // 53760 B

    cudaFuncSetAttribute(enc_nodes_kernel,    cudaFuncAttributeMaxDynamicSharedMemorySize, SM_ENC_N);
    cudaFuncSetAttribute(node_pre_mma,        cudaFuncAttributeMaxDynamicSharedMemorySize, SM_MMA2);
    cudaFuncSetAttribute(edge_persist_kernel, cudaFuncAttributeMaxDynamicSharedMemorySize, SM_EDGE);
    cudaFuncSetAttribute(update_mma,          cudaFuncAttributeMaxDynamicSharedMemorySize, SM_MMA2);

    const int SPLIT_TOTAL = 4*7*B_EL;
    const int ENC_N_BLOCKS = (Nn + 63) / 64;
    const int NODE_BLOCKS  = (Nn + 127) / 128;

    split_all_kernel<<<(SPLIT_TOTAL + 255)/256, 256>>>(
        msg_w1, msg_w2, upd_w1, upd_w2);                               // 1
    efconv_kernel<<<2048, 256>>>(ef);                                  // 2
    enc_nodes_kernel<<<ENC_N_BLOCKS, 256, SM_ENC_N>>>(nf, enc_node_w, enc_node_b); // 3
    wce_prec_kernel<<<(4*32*128 + 255)/256, 256>>>(msg_w1, enc_edge_w, enc_edge_b); // 4
    node_pre_mma<<<NODE_BLOCKS, 256, SM_MMA2>>>(cong, msg_w1, msg_b1, 0); // 5
    edge_persist_kernel<<<296, 256, SM_EDGE>>>(eidx, 0);               // 6
    zero_deg_kernel<<<(Nn + 1023)/1024, 1024>>>();                     // 7
    deg_accum_kernel<<<(Ee + 255)/256, 256>>>(eidx);                   // 8
    wprec_kernel<<<(4*B_EL + 255)/256, 256>>>(msg_w2, upd_w1, msg_b2); // 9

    for (int l = 0; l < 4; ++l) {
        if (l > 0)
            edge_persist_kernel<<<296, 256, SM_EDGE>>>(eidx, l);
        int hn = (l < 3) ? 1 : 0;
        update_mma<<<NODE_BLOCKS, 256, SM_MMA2>>>(
            upd_b1 + (size_t)l*128, upd_b2 + (size_t)l*128,
            ln_w + (size_t)l*128, ln_b + (size_t)l*128, l,
            cong,
            msg_w1 + (size_t)(l+1 < 4 ? l+1 : l)*385*128,
            msg_b1 + (size_t)(l+1 < 4 ? l+1 : l)*128,
            hn);
    }

    zero_red_kernel<<<1, 128>>>();
    reduce_kernel<<<250, 128>>>();
    final_kernel<<<1, 128>>>(mask, unr_w1, unr_b1, unr_w2, unr_b2,
                             ro_w1, ro_b1, ro_w2, ro_b2, ro_w3, ro_b3, out);
}

// round 15
// speedup vs baseline: 1.5588x; 1.2184x over previous
#include <cuda_runtime.h>
#include <cuda_bf16.h>
#include <math.h>

#define Nn 50000
#define Ee 800000
#define LDS 136       // smem row stride (bf16 elems) for 128-wide tiles
#define LDSE 40       // smem row stride for 32-wide ef tiles
#define B_EL 16384    // 128*128
#define WL   229376   // per-layer elems in g_w (14 * B_EL)

// ---------------- scratch (device globals; no allocation allowed) -----------
__device__ float          g_x  [(size_t)Nn*128];
__device__ __nv_bfloat16  g_xbf[(size_t)Nn*128];
__device__ __nv_bfloat16  g_xa [(size_t)Nn*128];
__device__ __nv_bfloat16  g_xb [(size_t)Nn*128];
__device__ __nv_bfloat16  g_agg[(size_t)Nn*128];   // aggregated h1 (bf16)
__device__ __nv_bfloat16  g_efbf[(size_t)Ee*32];   // ef in bf16
__device__ float          g_red[128];
__device__ float          g_deg[Nn];
__device__ float          g_v  [4*128];            // b2 @ U1b per layer
__device__ float          g_be [4*128];            // be @ W1e per layer
__device__ __nv_bfloat16  g_w[(size_t)4*WL];
__device__ __nv_bfloat16  g_wc [(size_t)4*2*B_EL]; // (W2@U1b) hi/lo per layer
__device__ __nv_bfloat16  g_wce[(size_t)4*4096];   // (We@W1e) hi per layer [32,128]

// ---------------- mma helpers ------------------------------------------------
__device__ __forceinline__ unsigned sptr(const void* p){
    return (unsigned)__cvta_generic_to_shared((void*)p);
}
__device__ __forceinline__ void ldsmA(unsigned a, unsigned &r0, unsigned &r1,
                                      unsigned &r2, unsigned &r3){
    asm volatile("ldmatrix.sync.aligned.m8n8.x4.shared.b16 {%0,%1,%2,%3},[%4];"
        : "=r"(r0),"=r"(r1),"=r"(r2),"=r"(r3) : "r"(a));
}
__device__ __forceinline__ void ldsmBT(unsigned a, unsigned &r0, unsigned &r1,
                                       unsigned &r2, unsigned &r3){
    asm volatile("ldmatrix.sync.aligned.m8n8.x4.trans.shared.b16 {%0,%1,%2,%3},[%4];"
        : "=r"(r0),"=r"(r1),"=r"(r2),"=r"(r3) : "r"(a));
}
__device__ __forceinline__ void mma_bf16(float* c, unsigned a0, unsigned a1,
                                         unsigned a2, unsigned a3,
                                         unsigned b0, unsigned b1){
    asm volatile("mma.sync.aligned.m16n8k16.row.col.f32.bf16.bf16.f32 "
        "{%0,%1,%2,%3},{%4,%5,%6,%7},{%8,%9},{%0,%1,%2,%3};"
        : "+f"(c[0]),"+f"(c[1]),"+f"(c[2]),"+f"(c[3])
        : "r"(a0),"r"(a1),"r"(a2),"r"(a3),"r"(b0),"r"(b1));
}
__device__ __forceinline__ unsigned packbf(float a, float b){
    __nv_bfloat162 h = __floats2bfloat162_rn(a, b);
    return *(unsigned*)&h;
}
__device__ __forceinline__ float2 unpackbf(unsigned u){
    __nv_bfloat162 h = *(__nv_bfloat162*)&u;
    return make_float2(__bfloat162float(h.x), __bfloat162float(h.y));
}
// 8-column bf16 vector atomic add (16B)
__device__ __forceinline__ void redbf8(__nv_bfloat16* p, unsigned a, unsigned b,
                                       unsigned c, unsigned d){
    asm volatile("red.global.add.noftz.v4.bf16x2 [%0], {%1,%2,%3,%4};"
        :: "l"(p), "r"(a), "r"(b), "r"(c), "r"(d) : "memory");
}
__device__ __forceinline__ void pref_l1(const void* p){
    asm volatile("prefetch.global.L1 [%0];" :: "l"(p));
}

// -------- fused weight pre-split (ONE launch): hi=bf16(w), lo=bf16(w-hi) ----
__global__ void split_all_kernel(const float* __restrict__ msg_w1,
                                 const float* __restrict__ msg_w2,
                                 const float* __restrict__ upd_w1,
                                 const float* __restrict__ upd_w2){
    const int PER_L = 7*B_EL;
    int i = blockIdx.x*blockDim.x + threadIdx.x;
    if (i >= 4*PER_L) return;
    float w; size_t hid; size_t lstep;
    int l = i / PER_L, k = i % PER_L;
    size_t base = (size_t)l*WL;
    if (k < 3*B_EL) {                       // W1a, W1b, W1e
        w = msg_w1[(size_t)l*385*128 + k];
        int blk = k / B_EL, off = k % B_EL;
        hid = base + (size_t)(2*blk)*B_EL + off; lstep = B_EL;
    } else if (k < 4*B_EL) {                // W2
        int off = k - 3*B_EL;
        w = msg_w2[(size_t)l*B_EL + off];
        hid = base + (size_t)6*B_EL + off; lstep = B_EL;
    } else if (k < 6*B_EL) {                // U1 (2 blocks)
        int off = k - 4*B_EL;
        w = upd_w1[(size_t)l*2*B_EL + off];
        hid = base + (size_t)8*B_EL + off; lstep = 2*B_EL;
    } else {                                // U2
        int off = k - 6*B_EL;
        w = upd_w2[(size_t)l*B_EL + off];
        hid = base + (size_t)12*B_EL + off; lstep = B_EL;
    }
    __nv_bfloat16 h = __float2bfloat16(w);
    g_w[hid] = h;
    g_w[hid + lstep] = __float2bfloat16(w - __bfloat162float(h));
}

// -------- ef -> bf16 (once) -------------------------------------------------
__global__ void efconv_kernel(const float* __restrict__ ef){
    size_t i = (size_t)blockIdx.x*blockDim.x + threadIdx.x;
    size_t n = (size_t)Ee*32;
    for (; i < n; i += (size_t)gridDim.x*blockDim.x)
        g_efbf[i] = __float2bfloat16(ef[i]);
}

// -------- composite edge weight: Wce = We@W1e (hi only), g_be = be@W1e ------
__global__ void wce_prec_kernel(const float* __restrict__ msg_w1,
                                const float* __restrict__ enc_edge_w,
                                const float* __restrict__ enc_edge_b){
    int idx = blockIdx.x*blockDim.x + threadIdx.x;
    if (idx >= 4*32*128) return;
    int l = idx >> 12; int ij = idx & 4095;
    int i = ij >> 7, j = ij & 127;
    const float* W1e = msg_w1 + (size_t)l*385*128 + 256*128;
    float c = 0.f;
#pragma unroll 4
    for (int k = 0; k < 128; ++k)
        c = fmaf(enc_edge_w[i*128 + k], W1e[k*128 + j], c);
    g_wce[(size_t)l*4096 + ij] = __float2bfloat16(c);
    if (i == 0) {
        float v = 0.f;
#pragma unroll 4
        for (int k = 0; k < 128; ++k)
            v = fmaf(enc_edge_b[k], W1e[k*128 + j], v);
        g_be[l*128 + j] = v;
    }
}

// -------- composite update weight: C = W2@U1b, v = b2@U1b -------------------
__global__ void wprec_kernel(const float* __restrict__ msg_w2,
                             const float* __restrict__ upd_w1,
                             const float* __restrict__ msg_b2){
    int idx = blockIdx.x*blockDim.x + threadIdx.x;
    if (idx >= 4*B_EL) return;
    int l = idx >> 14; int ij = idx & 16383;
    int i = ij >> 7, j = ij & 127;
    const float* W2  = msg_w2 + (size_t)l*B_EL;
    const float* U1b = upd_w1 + (size_t)l*2*B_EL + B_EL;
    float c = 0.f;
#pragma unroll 4
    for (int k = 0; k < 128; ++k)
        c = fmaf(W2[i*128 + k], U1b[k*128 + j], c);
    __nv_bfloat16 h = __float2bfloat16(c);
    g_wc[(size_t)l*2*B_EL + ij] = h;
    g_wc[(size_t)l*2*B_EL + B_EL + ij] = __float2bfloat16(c - __bfloat162float(h));
    if (i == 0) {
        float v = 0.f;
#pragma unroll 4
        for (int k = 0; k < 128; ++k)
            v = fmaf(msg_b2[l*128 + k], U1b[k*128 + j], v);
        g_v[l*128 + j] = v;
    }
}

// -------- degree (once) -----------------------------------------------------
__global__ void zero_deg_kernel(){
    int i = blockIdx.x*blockDim.x + threadIdx.x;
    if (i < Nn) g_deg[i] = 0.f;
}
__global__ void deg_accum_kernel(const int* __restrict__ eidx){
    int i = blockIdx.x*blockDim.x + threadIdx.x;
    if (i < Ee) atomicAdd(&g_deg[eidx[(size_t)Ee + i]], 1.f);
}

// Load dense bf16 [128][128] weight into SMEM [128][LDS].  256 threads.
__device__ __forceinline__ void load_wbf(const __nv_bfloat16* __restrict__ Wd,
                                         __nv_bfloat16* sW, int tid){
#pragma unroll
    for (int it = 0; it < 8; ++it){
        int idx = tid + it*256;
        int row = idx >> 4, c = idx & 15;
        *(uint4*)(sW + row*LDS + c*8) = __ldg((const uint4*)Wd + idx);
    }
}

// Warp-level 16x128 @ 128x128 mma accumulate. Warp w owns rows w*16..w*16+15.
__device__ __forceinline__ void mma_gemm128(const __nv_bfloat16* sA,
                                            const __nv_bfloat16* sW,
                                            float acc[16][4], int warp, int lane){
    unsigned aB = sptr(sA + (warp*16 + (lane & 15))*LDS + (lane >> 4)*8);
    unsigned bB = sptr(sW + (lane & 15)*LDS + (lane >> 4)*8);
#pragma unroll
    for (int kk = 0; kk < 8; ++kk){
        unsigned a0,a1,a2,a3;
        ldsmA(aB + kk*32, a0,a1,a2,a3);
#pragma unroll
        for (int jp = 0; jp < 8; ++jp){
            unsigned b0,b1,b2,b3;
            ldsmBT(bB + kk*(16*LDS*2) + jp*32, b0,b1,b2,b3);
            mma_bf16(acc[2*jp],   a0,a1,a2,a3, b0,b1);
            mma_bf16(acc[2*jp+1], a0,a1,a2,a3, b2,b3);
        }
    }
}

// ---------------- node encoder (fp32 FFMA) ----------------------------------
__global__ void enc_nodes_kernel(const float* __restrict__ nf,
                                 const float* __restrict__ W,
                                 const float* __restrict__ b) {
    extern __shared__ float sm[];
    float* sIn = sm;
    float* sW  = sm + 64*64;
    int tid = threadIdx.x, warp = tid >> 5, lane = tid & 31;
    int rb = blockIdx.x * 64;
#pragma unroll
    for (int it = 0; it < 4; ++it) {
        int idx = tid + it*256;
        int row = idx >> 4, c4 = idx & 15;
        int r = rb + row; if (r >= Nn) r = Nn - 1;
        ((float4*)sIn)[idx] = ((const float4*)(nf + (size_t)r*64))[c4];
    }
#pragma unroll
    for (int it = 0; it < 8; ++it) {
        int idx = tid + it*256;
        ((float4*)sW)[idx] = ((const float4*)W)[idx];
    }
    __syncthreads();
    float acc[8][4];
#pragma unroll
    for (int i = 0; i < 8; ++i) { acc[i][0]=acc[i][1]=acc[i][2]=acc[i][3]=0.f; }
#pragma unroll 8
    for (int k = 0; k < 64; ++k) {
        float4 w = ((float4*)(sW + k*128))[lane];
#pragma unroll
        for (int i = 0; i < 8; ++i) {
            float a = sIn[(warp*8 + i)*64 + k];
            acc[i][0] = fmaf(a, w.x, acc[i][0]);
            acc[i][1] = fmaf(a, w.y, acc[i][1]);
            acc[i][2] = fmaf(a, w.z, acc[i][2]);
            acc[i][3] = fmaf(a, w.w, acc[i][3]);
        }
    }
    float4 bb = ((const float4*)b)[lane];
#pragma unroll
    for (int i = 0; i < 8; ++i) {
        int r = rb + warp*8 + i;
        if (r < Nn) {
            float4 v = make_float4(acc[i][0]+bb.x, acc[i][1]+bb.y,
                                   acc[i][2]+bb.z, acc[i][3]+bb.w);
            ((float4*)(g_x + (size_t)r*128))[lane] = v;
            *(uint2*)(g_xbf + (size_t)r*128 + lane*4) =
                make_uint2(packbf(v.x, v.y), packbf(v.z, v.w));
        }
    }
}

// --------- xa/xb epilogue + GEMMs from an sA tile already in SMEM -----------
__device__ __forceinline__ void node_pre_body(
        __nv_bfloat16* sA, __nv_bfloat16* sW,
        const float* cong, const float* w1l, const float* b1,
        const __nv_bfloat16* wb, int layer, int rb,
        int tid, int warp, int lane){
    float acc[16][4];
#pragma unroll
    for (int j = 0; j < 16; ++j) { acc[j][0]=acc[j][1]=acc[j][2]=acc[j][3]=0.f; }
#pragma unroll 1
    for (int ph = 0; ph < 2; ++ph) {
        __syncthreads();
        load_wbf(wb + (size_t)ph*B_EL, sW, tid);
        __syncthreads();
        mma_gemm128(sA, sW, acc, warp, lane);
    }
    int g = lane >> 2, t4 = lane & 3;
    int r0 = rb + warp*16 + g, r1 = r0 + 8;
    float c0 = cong[r0 < Nn ? r0 : Nn-1];
    float c1 = cong[r1 < Nn ? r1 : Nn-1];
#pragma unroll
    for (int j = 0; j < 16; ++j) {
        int col = j*8 + t4*2;
        float2 wc = *(const float2*)(w1l + 384*128 + col);
        float2 bb = *(const float2*)(b1 + col);
        float2 be = *(const float2*)(g_be + layer*128 + col);
        bb.x += be.x; bb.y += be.y;
        if (r0 < Nn)
            *(unsigned*)(g_xa + (size_t)r0*128 + col) =
                packbf(acc[j][0] + c0*wc.x + bb.x, acc[j][1] + c0*wc.y + bb.y);
        if (r1 < Nn)
            *(unsigned*)(g_xa + (size_t)r1*128 + col) =
                packbf(acc[j][2] + c1*wc.x + bb.x, acc[j][3] + c1*wc.y + bb.y);
        acc[j][0]=acc[j][1]=acc[j][2]=acc[j][3]=0.f;
    }
#pragma unroll 1
    for (int ph = 0; ph < 2; ++ph) {
        __syncthreads();
        load_wbf(wb + (size_t)(2+ph)*B_EL, sW, tid);
        __syncthreads();
        mma_gemm128(sA, sW, acc, warp, lane);
    }
#pragma unroll
    for (int j = 0; j < 16; ++j) {
        int col = j*8 + t4*2;
        if (r0 < Nn)
            *(unsigned*)(g_xb + (size_t)r0*128 + col) = packbf(acc[j][0], acc[j][1]);
        if (r1 < Nn)
            *(unsigned*)(g_xb + (size_t)r1*128 + col) = packbf(acc[j][2], acc[j][3]);
    }
}

// --------- layer-0 node precompute + agg zero -------------------------------
__global__ void __launch_bounds__(256,2) node_pre_mma(const float* __restrict__ cong,
                                 const float* __restrict__ w1l,
                                 const float* __restrict__ b1,
                                 int layer) {
    extern __shared__ __nv_bfloat16 smx[];
    __nv_bfloat16* sA = smx;
    __nv_bfloat16* sW = smx + 128*LDS;
    const __nv_bfloat16* wb = g_w + (size_t)layer*WL;
    int tid = threadIdx.x, warp = tid >> 5, lane = tid & 31;
    int rb = blockIdx.x * 128;
    uint4 z4 = make_uint4(0,0,0,0);
#pragma unroll
    for (int it = 0; it < 8; ++it) {
        int idx = tid + it*256;
        int row = idx >> 4, c = idx & 15;
        int r = rb + row;
        if (r < Nn) ((uint4*)(g_agg + (size_t)r*128))[c] = z4;
    }
#pragma unroll
    for (int it = 0; it < 8; ++it) {
        int idx = tid + it*256; int row = idx >> 4, c = idx & 15;
        int r = rb + row; if (r >= Nn) r = Nn - 1;
        *(uint4*)(sA + row*LDS + c*8) = __ldg((const uint4*)(g_xbf + (size_t)r*128) + c);
    }
    node_pre_body(sA, sW, cong, w1l, b1, wb, layer, rb, tid, warp, lane);
}

__global__ void zero_red_kernel() { if (threadIdx.x < 128) g_red[threadIdx.x] = 0.f; }

// ------- persistent edge kernel: K=32 composite GEMM (hi-only) + h1 scatter -
// h1 = relu(ef@Wce + xa[src] + xb[dst]); agg[dst] += h1 (bf16x2 v4 atomics)
__global__ void __launch_bounds__(256,2) edge_persist_kernel(
                                const int* __restrict__ eidx, int layer) {
    extern __shared__ __nv_bfloat16 smx[];
    __nv_bfloat16* sEF = smx;                       // 128 x LDSE (ef bf16)
    __nv_bfloat16* sW  = smx + 128*LDSE;            // 32 x LDS (hi only)
    __nv_bfloat16* sG  = smx + 128*LDSE + 32*LDS;   // 128 x LDS (gather)
    __shared__ int sSe[128], sDe[128];
    int tid = threadIdx.x, w = tid >> 5, lane = tid & 31;

    // composite weight hi: 32 rows x 16 uint4 = 512 uint4
#pragma unroll
    for (int it = 0; it < 2; ++it) {
        int idx = tid + it*256;
        int row = idx >> 4, c = idx & 15;
        *(uint4*)(sW + row*LDS + c*8) =
            __ldg((const uint4*)(g_wce + (size_t)layer*4096) + idx);
    }
    __syncthreads();

    int g = lane >> 2, t4 = lane & 3;

    for (int t = blockIdx.x; t < Ee/128; t += gridDim.x) {
        size_t eb = (size_t)t * 128;
        __syncwarp();                         // prev tile fully consumed (warp-local)
        if (lane < 16) sSe[w*16 + lane] = eidx[eb + w*16 + lane];
        else           sDe[w*16 + lane - 16] = eidx[(size_t)Ee + eb + w*16 + lane - 16];
        __syncwarp();
        // L1-prefetch gather lines (own 16 rows; 2 x 128B lines per row)
        {
            int lr = lane & 15, row = w*16 + lr;
            if (lane < 16) {
                const char* p = (const char*)(g_xa + (size_t)sSe[row]*128);
                pref_l1(p); pref_l1(p + 128);
            } else {
                const char* p = (const char*)(g_xb + (size_t)sDe[row]*128);
                pref_l1(p); pref_l1(p + 128);
            }
        }
        // own 16 ef rows (32 bf16 each): 64 uint4 per warp, 2 per lane
#pragma unroll
        for (int k = 0; k < 2; ++k) {
            int idx = lane + k*32; int lr = idx >> 2, c = idx & 3;
            *(uint4*)(sEF + (w*16 + lr)*LDSE + c*8) =
                __ldg((const uint4*)(g_efbf + (eb + w*16 + lr)*32) + c);
        }
        __syncwarp();
        float acc[16][4];
#pragma unroll
        for (int j = 0; j < 16; ++j) { acc[j][0]=acc[j][1]=acc[j][2]=acc[j][3]=0.f; }
        // GEMM: K=32, hi only
        unsigned aB = sptr(sEF + (w*16 + (lane & 15))*LDSE + (lane >> 4)*8);
        unsigned bB = sptr(sW + (lane & 15)*LDS + (lane >> 4)*8);
#pragma unroll
        for (int kk = 0; kk < 2; ++kk) {
            unsigned a0,a1,a2,a3;
            ldsmA(aB + kk*32, a0,a1,a2,a3);
#pragma unroll
            for (int jp = 0; jp < 8; ++jp) {
                unsigned b0,b1,b2,b3;
                ldsmBT(bB + kk*(16*LDS*2) + jp*32, b0,b1,b2,b3);
                mma_bf16(acc[2*jp],   a0,a1,a2,a3, b0,b1);
                mma_bf16(acc[2*jp+1], a0,a1,a2,a3, b2,b3);
            }
        }
        // gather xa[src]+xb[dst] -> own sG rows (should hit L1)
#pragma unroll
        for (int k = 0; k < 8; ++k) {
            int idx = lane + k*32; int lr = idx >> 4, c = idx & 15;
            int row = w*16 + lr;
            uint4 a = __ldg((const uint4*)(g_xa + (size_t)sSe[row]*128) + c);
            uint4 b = __ldg((const uint4*)(g_xb + (size_t)sDe[row]*128) + c);
            uint4 r;
            ((__nv_bfloat162&)r.x) = __hadd2(((__nv_bfloat162&)a.x), ((__nv_bfloat162&)b.x));
            ((__nv_bfloat162&)r.y) = __hadd2(((__nv_bfloat162&)a.y), ((__nv_bfloat162&)b.y));
            ((__nv_bfloat162&)r.z) = __hadd2(((__nv_bfloat162&)a.z), ((__nv_bfloat162&)b.z));
            ((__nv_bfloat162&)r.w) = __hadd2(((__nv_bfloat162&)a.w), ((__nv_bfloat162&)b.w));
            *(uint4*)(sG + row*LDS + c*8) = r;
        }
        __syncwarp();
        // h1 = relu(acc + gather); quad-transpose to 8-col vectors; bf16x2 v4 red
        int dst0 = sDe[w*16 + g], dst1 = sDe[w*16 + g + 8];
#pragma unroll
        for (int j = 0; j < 16; j += 2) {
            unsigned r0v, r1v, r2v, r3v;
            {
                int col = j*8 + t4*2;
                float2 g0 = unpackbf(*(unsigned*)(sG + (w*16 + g)*LDS + col));
                float2 g1 = unpackbf(*(unsigned*)(sG + (w*16 + g + 8)*LDS + col));
                r0v = packbf(fmaxf(acc[j][0] + g0.x, 0.f), fmaxf(acc[j][1] + g0.y, 0.f));
                r1v = packbf(fmaxf(acc[j][2] + g1.x, 0.f), fmaxf(acc[j][3] + g1.y, 0.f));
            }
            {
                int col = (j+1)*8 + t4*2;
                float2 g0 = unpackbf(*(unsigned*)(sG + (w*16 + g)*LDS + col));
                float2 g1 = unpackbf(*(unsigned*)(sG + (w*16 + g + 8)*LDS + col));
                r2v = packbf(fmaxf(acc[j+1][0] + g0.x, 0.f), fmaxf(acc[j+1][1] + g0.y, 0.f));
                r3v = packbf(fmaxf(acc[j+1][2] + g1.x, 0.f), fmaxf(acc[j+1][3] + g1.y, 0.f));
            }
            // 4x4 quad transpose (2 butterfly stages, 4 shuffles)
            unsigned a = (t4 & 1) ? r0v : r1v;
            a = __shfl_xor_sync(0xffffffffu, a, 1);
            if (t4 & 1) r0v = a; else r1v = a;
            unsigned b = (t4 & 1) ? r2v : r3v;
            b = __shfl_xor_sync(0xffffffffu, b, 1);
            if (t4 & 1) r2v = b; else r3v = b;
            unsigned c2 = (t4 & 2) ? r0v : r2v;
            c2 = __shfl_xor_sync(0xffffffffu, c2, 2);
            if (t4 & 2) r0v = c2; else r2v = c2;
            unsigned d2 = (t4 & 2) ? r1v : r3v;
            d2 = __shfl_xor_sync(0xffffffffu, d2, 2);
            if (t4 & 2) r1v = d2; else r3v = d2;
            // thread t4 now owns 8 cols of: t0:(dst0,j) t1:(dst1,j) t2:(dst0,j+1) t3:(dst1,j+1)
            int dsel = (t4 & 1) ? dst1 : dst0;
            int jj = (t4 & 2) ? (j + 1) : j;
            redbf8(g_agg + (size_t)dsel*128 + jj*8, r0v, r1v, r2v, r3v);
        }
    }
}

// ------- update (mma) + fused next-layer node precompute --------------------
__global__ void __launch_bounds__(256,2) update_mma(const float* __restrict__ ub1,
                               const float* __restrict__ ub2,
                               const float* __restrict__ lw,
                               const float* __restrict__ lb,
                               int layer,
                               const float* __restrict__ cong,
                               const float* __restrict__ w1l_next,
                               const float* __restrict__ b1_next,
                               int has_next) {
    extern __shared__ __nv_bfloat16 smx[];
    __nv_bfloat16* sA = smx;
    __nv_bfloat16* sW = smx + 128*LDS;
    const __nv_bfloat16* wb = g_w + (size_t)layer*WL;
    int tid = threadIdx.x, warp = tid >> 5, lane = tid & 31;
    int rb = blockIdx.x * 128;
    float acc[16][4];
#pragma unroll
    for (int j = 0; j < 16; ++j) { acc[j][0]=acc[j][1]=acc[j][2]=acc[j][3]=0.f; }
#pragma unroll 1
    for (int kc = 0; kc < 2; ++kc) {
        __syncthreads();
        if (kc == 0) {
#pragma unroll
            for (int it = 0; it < 8; ++it) {
                int idx = tid + it*256; int row = idx >> 4, c = idx & 15;
                int r = rb + row; if (r >= Nn) r = Nn - 1;
                *(uint4*)(sA + row*LDS + c*8) =
                    __ldg((const uint4*)(g_xbf + (size_t)r*128) + c);
            }
        } else {
#pragma unroll
            for (int it = 0; it < 8; ++it) {
                int idx = tid + it*256; int row = idx >> 4, c = idx & 15;
                int r = rb + row; if (r >= Nn) r = Nn - 1;
                *(uint4*)(sA + row*LDS + c*8) =
                    __ldg((const uint4*)(g_agg + (size_t)r*128) + c);
            }
        }
#pragma unroll 1
        for (int ph = 0; ph < 2; ++ph) {
            __syncthreads();
            const __nv_bfloat16* ws = (kc == 0)
                ? wb + (size_t)(8 + ph*2)*B_EL
                : g_wc + (size_t)layer*2*B_EL + (size_t)ph*B_EL;
            load_wbf(ws, sW, tid);
            __syncthreads();
            mma_gemm128(sA, sW, acc, warp, lane);
        }
    }
    __syncthreads();
    int g = lane >> 2, t4 = lane & 3;
    int r0 = rb + warp*16 + g, r1 = r0 + 8;
    int r0c = r0 < Nn ? r0 : Nn-1, r1c = r1 < Nn ? r1 : Nn-1;
    float dg0 = g_deg[r0c], dg1 = g_deg[r1c];
#pragma unroll
    for (int j = 0; j < 16; ++j) {
        int col = j*8 + t4*2;
        float2 bb = *(const float2*)(ub1 + col);
        float2 vv = *(const float2*)(g_v + layer*128 + col);
#pragma unroll
        for (int rr = 0; rr < 2; ++rr) {
            int row = warp*16 + g + rr*8;
            float dg = rr ? dg1 : dg0;
            float h0 = fmaxf(acc[j][2*rr]   + bb.x + dg*vv.x, 0.f);
            float h1 = fmaxf(acc[j][2*rr+1] + bb.y + dg*vv.y, 0.f);
            *(unsigned*)(sA + row*LDS + col) = packbf(h0, h1);
            acc[j][2*rr] = 0.f; acc[j][2*rr+1] = 0.f;
        }
    }
#pragma unroll 1
    for (int ph = 0; ph < 2; ++ph) {
        __syncthreads();
        load_wbf(wb + (size_t)(12 + ph)*B_EL, sW, tid);
        __syncthreads();
        mma_gemm128(sA, sW, acc, warp, lane);
    }
    float s0 = 0.f, s1 = 0.f;
#pragma unroll
    for (int j = 0; j < 16; ++j) {
        int col = j*8 + t4*2;
        float2 bb = *(const float2*)(ub2 + col);
        float2 x0 = *(const float2*)(g_x + (size_t)r0c*128 + col);
        float2 x1 = *(const float2*)(g_x + (size_t)r1c*128 + col);
        acc[j][0] += x0.x + bb.x;  acc[j][1] += x0.y + bb.y;
        acc[j][2] += x1.x + bb.x;  acc[j][3] += x1.y + bb.y;
        s0 += acc[j][0] + acc[j][1];
        s1 += acc[j][2] + acc[j][3];
    }
    s0 += __shfl_xor_sync(0xffffffffu, s0, 1);
    s0 += __shfl_xor_sync(0xffffffffu, s0, 2);
    s1 += __shfl_xor_sync(0xffffffffu, s1, 1);
    s1 += __shfl_xor_sync(0xffffffffu, s1, 2);
    float mu0 = s0 * (1.f/128.f), mu1 = s1 * (1.f/128.f);
    float q0 = 0.f, q1 = 0.f;
#pragma unroll
    for (int j = 0; j < 16; ++j) {
        float d0 = acc[j][0]-mu0, d1 = acc[j][1]-mu0;
        float d2 = acc[j][2]-mu1, d3 = acc[j][3]-mu1;
        q0 += d0*d0 + d1*d1;
        q1 += d2*d2 + d3*d3;
    }
    q0 += __shfl_xor_sync(0xffffffffu, q0, 1);
    q0 += __shfl_xor_sync(0xffffffffu, q0, 2);
    q1 += __shfl_xor_sync(0xffffffffu, q1, 1);
    q1 += __shfl_xor_sync(0xffffffffu, q1, 2);
    float rstd0 = rsqrtf(q0 * (1.f/128.f) + 1e-5f);
    float rstd1 = rsqrtf(q1 * (1.f/128.f) + 1e-5f);
    __syncwarp();   // own-warp ldmatrix of sA (h1) done before overwrite
#pragma unroll
    for (int j = 0; j < 16; ++j) {
        int col = j*8 + t4*2;
        float2 lw2 = *(const float2*)(lw + col);
        float2 lb2 = *(const float2*)(lb + col);
        float o0 = (acc[j][0]-mu0)*rstd0*lw2.x + lb2.x;
        float o1 = (acc[j][1]-mu0)*rstd0*lw2.y + lb2.y;
        float o2 = (acc[j][2]-mu1)*rstd1*lw2.x + lb2.x;
        float o3 = (acc[j][3]-mu1)*rstd1*lw2.y + lb2.y;
        if (r0 < Nn) {
            *(float2*)(g_x + (size_t)r0*128 + col) = make_float2(o0, o1);
            *(unsigned*)(g_xbf + (size_t)r0*128 + col) = packbf(o0, o1);
        }
        if (r1 < Nn) {
            *(float2*)(g_x + (size_t)r1*128 + col) = make_float2(o2, o3);
            *(unsigned*)(g_xbf + (size_t)r1*128 + col) = packbf(o2, o3);
        }
        int row0 = warp*16 + g, row1 = row0 + 8;
        *(unsigned*)(sA + row0*LDS + col) = packbf(o0, o1);
        *(unsigned*)(sA + row1*LDS + col) = packbf(o2, o3);
    }
    if (!has_next) return;
    uint4 z4 = make_uint4(0,0,0,0);
#pragma unroll
    for (int it = 0; it < 8; ++it) {
        int idx = tid + it*256;
        int row = idx >> 4, c = idx & 15;
        int r = rb + row;
        if (r < Nn) ((uint4*)(g_agg + (size_t)r*128))[c] = z4;
    }
    node_pre_body(sA, sW, cong, w1l_next, b1_next,
                  g_w + (size_t)(layer+1)*WL, layer+1, rb, tid, warp, lane);
}

// ---------------- column-sum reduce + readout -------------------------------
__global__ void reduce_kernel() {
    int j = threadIdx.x;
    int chunk = (Nn + gridDim.x - 1) / gridDim.x;
    int r0 = blockIdx.x * chunk;
    int r1 = r0 + chunk; if (r1 > Nn) r1 = Nn;
    float s = 0.f;
    for (int r = r0; r < r1; ++r) s += g_x[(size_t)r*128 + j];
    atomicAdd(&g_red[j], s);
}

__global__ void final_kernel(const void* __restrict__ maskp,
                             const float* __restrict__ uw1, const float* __restrict__ ub1f,
                             const float* __restrict__ uw2, const float* __restrict__ ub2f,
                             const float* __restrict__ rw1, const float* __restrict__ rb1,
                             const float* __restrict__ rw2, const float* __restrict__ rb2,
                             const float* __restrict__ rw3, const float* __restrict__ rb3,
                             float* __restrict__ out) {
    __shared__ float sge[128], s1[128], s2[128];
    __shared__ int c1s, c2s;
    __shared__ float sufs;
    int j = threadIdx.x;
    if (j == 0) { c1s = 0; c2s = 0; sufs = 0.f; }
    __syncthreads();
    const unsigned char* mb = (const unsigned char*)maskp;
    int c1 = 0, c2 = 0;
    for (int i = j; i < Nn; i += 128) {
        unsigned char v = mb[i];
        if (v) { if ((i & 3) == 0) c1++; else c2++; }
    }
    atomicAdd(&c1s, c1); atomicAdd(&c2s, c2);
    __syncthreads();
    float s = 0.f;
    if (c2s == 0) {
        const int* mi = (const int*)maskp;
        for (int i = j; i < Nn; i += 128) s += (mi[i] != 0) ? 1.f : 0.f;
    } else if (c1s == 0) {
        const float* mf = (const float*)maskp;
        for (int i = j; i < Nn; i += 128) s += mf[i];
    } else {
        for (int i = j; i < Nn; i += 128) s += mb[i] ? 1.f : 0.f;
    }
    atomicAdd(&sufs, s);
    sge[j] = g_red[j] * (1.f/(float)Nn);
    __syncthreads();
    float uf = sufs * (1.f/(float)Nn);
    s1[j] = fmaxf(uf * uw1[j] + ub1f[j], 0.f);
    __syncthreads();
    float t = ub2f[j];
    for (int k = 0; k < 128; ++k) t = fmaf(s1[k], uw2[k*128 + j], t);
    s2[j] = t;
    __syncthreads();
    float h = rb1[j];
    for (int k = 0; k < 128; ++k) h = fmaf(sge[k], rw1[k*128 + j], h);
    for (int k = 0; k < 128; ++k) h = fmaf(s2[k], rw1[(128 + k)*128 + j], h);
    s1[j] = fmaxf(h, 0.f);
    __syncthreads();
    if (j < 64) {
        float gv = rb2[j];
        for (int k = 0; k < 128; ++k) gv = fmaf(s1[k], rw2[k*64 + j], gv);
        s2[j] = fmaxf(gv, 0.f);
    }
    __syncthreads();
    if (j == 0) {
        float o = rb3[0];
        for (int k = 0; k < 64; ++k) o = fmaf(s2[k], rw3[k], o);
        out[0] = 1.f / (1.f + expf(-o));
    }
}

// ---------------- launch -----------------------------------------------------
extern "C" void kernel_launch(void* const* d_in, const int* in_sizes, int n_in,
                              void* d_out, int out_size) {
    const float* nf        = (const float*)d_in[0];
    const float* ef        = (const float*)d_in[1];
    const float* cong      = (const float*)d_in[2];
    const int*   eidx      = (const int*)d_in[3];
    const void*  mask      = d_in[4];
    const float* enc_node_w = (const float*)d_in[5];
    const float* enc_node_b = (const float*)d_in[6];
    const float* enc_edge_w = (const float*)d_in[7];
    const float* enc_edge_b = (const float*)d_in[8];
    const float* msg_w1 = (const float*)d_in[9];
    const float* msg_b1 = (const float*)d_in[10];
    const float* msg_w2 = (const float*)d_in[11];
    const float* msg_b2 = (const float*)d_in[12];
    const float* upd_w1 = (const float*)d_in[13];
    const float* upd_b1 = (const float*)d_in[14];
    const float* upd_w2 = (const float*)d_in[15];
    const float* upd_b2 = (const float*)d_in[16];
    const float* ln_w   = (const float*)d_in[17];
    const float* ln_b   = (const float*)d_in[18];
    const float* unr_w1 = (const float*)d_in[19];
    const float* unr_b1 = (const float*)d_in[20];
    const float* unr_w2 = (const float*)d_in[21];
    const float* unr_b2 = (const float*)d_in[22];
    const float* ro_w1  = (const float*)d_in[23];
    const float* ro_b1  = (const float*)d_in[24];
    const float* ro_w2  = (const float*)d_in[25];
    const float* ro_b2  = (const float*)d_in[26];
    const float* ro_w3  = (const float*)d_in[27];
    const float* ro_b3  = (const float*)d_in[28];
    float* out = (float*)d_out;

    const int SM_ENC_N = (64*64 + 64*128) * 4;
    const int SM_MMA2  = 2 * 128 * LDS * 2;                      // 69632 B
    const int SM_EDGE  = (128*LDSE + 32*LDS + 128*LDS) * 2;      // 53760 B

    cudaFuncSetAttribute(enc_nodes_kernel,    cudaFuncAttributeMaxDynamicSharedMemorySize, SM_ENC_N);
    cudaFuncSetAttribute(node_pre_mma,        cudaFuncAttributeMaxDynamicSharedMemorySize, SM_MMA2);
    cudaFuncSetAttribute(edge_persist_kernel, cudaFuncAttributeMaxDynamicSharedMemorySize, SM_EDGE);
    cudaFuncSetAttribute(update_mma,          cudaFuncAttributeMaxDynamicSharedMemorySize, SM_MMA2);

    const int SPLIT_TOTAL = 4*7*B_EL;
    const int ENC_N_BLOCKS = (Nn + 63) / 64;
    const int NODE_BLOCKS  = (Nn + 127) / 128;

    split_all_kernel<<<(SPLIT_TOTAL + 255)/256, 256>>>(
        msg_w1, msg_w2, upd_w1, upd_w2);                               // 1
    efconv_kernel<<<2048, 256>>>(ef);                                  // 2
    enc_nodes_kernel<<<ENC_N_BLOCKS, 256, SM_ENC_N>>>(nf, enc_node_w, enc_node_b); // 3
    wce_prec_kernel<<<(4*32*128 + 255)/256, 256>>>(msg_w1, enc_edge_w, enc_edge_b); // 4
    node_pre_mma<<<NODE_BLOCKS, 256, SM_MMA2>>>(cong, msg_w1, msg_b1, 0); // 5
    edge_persist_kernel<<<296, 256, SM_EDGE>>>(eidx, 0);               // 6
    zero_deg_kernel<<<(Nn + 1023)/1024, 1024>>>();                     // 7
    deg_accum_kernel<<<(Ee + 255)/256, 256>>>(eidx);                   // 8
    wprec_kernel<<<(4*B_EL + 255)/256, 256>>>(msg_w2, upd_w1, msg_b2); // 9

    for (int l = 0; l < 4; ++l) {
        if (l > 0)
            edge_persist_kernel<<<296, 256, SM_EDGE>>>(eidx, l);
        int hn = (l < 3) ? 1 : 0;
        update_mma<<<NODE_BLOCKS, 256, SM_MMA2>>>(
            upd_b1 + (size_t)l*128, upd_b2 + (size_t)l*128,
            ln_w + (size_t)l*128, ln_b + (size_t)l*128, l,
            cong,
            msg_w1 + (size_t)(l+1 < 4 ? l+1 : l)*385*128,
            msg_b1 + (size_t)(l+1 < 4 ? l+1 : l)*128,
            hn);
    }

    zero_red_kernel<<<1, 128>>>();
    reduce_kernel<<<250, 128>>>();
    final_kernel<<<1, 128>>>(mask, unr_w1, unr_b1, unr_w2, unr_b2,
                             ro_w1, ro_b1, ro_w2, ro_b2, ro_w3, ro_b3, out);
}